// round 11
// baseline (speedup 1.0000x reference)
#include <cuda_runtime.h>
#include <cuda_bf16.h>

// ---------------------------------------------------------------------------
// Problem constants
// ---------------------------------------------------------------------------
#define BATCH 8
#define CHANNELS 1024
#define HW 2304           // 48*48
#define POOL_P 576        // 24*24
#define POS_TOTAL (BATCH*POOL_P*POOL_P)   // 2,654,208
#define EPS_L2 1e-6f
#define EPS_MM 1e-5f

typedef unsigned long long u64;

// ---------------------------------------------------------------------------
// Scratch (device globals; no allocation allowed)
// ---------------------------------------------------------------------------
__device__ float g_A[BATCH * HW * CHANNELS];
__device__ float g_B[BATCH * HW * CHANNELS];
__device__ float g_invnA[BATCH * HW];
__device__ float g_invnB[BATCH * HW];
__device__ float g_cpool[POS_TOTAL];
__device__ float g_x1[BATCH * 10 * POOL_P * POOL_P];
__device__ float g_x2[BATCH * 10 * POOL_P * POOL_P];
__device__ float g_amax[BATCH * POOL_P];      // reciprocals 1/(max+eps)
__device__ float g_bmax[BATCH * POOL_P];

// ---------------------------------------------------------------------------
// Helpers
// ---------------------------------------------------------------------------
__device__ __forceinline__ unsigned smem_u32(const void* p) {
    return (unsigned)__cvta_generic_to_shared(p);
}
__device__ __forceinline__ u64 pack2(float a, float b) {
    u64 r; asm("mov.b64 %0, {%1, %2};" : "=l"(r) : "f"(a), "f"(b)); return r;
}
__device__ __forceinline__ void fma2(u64& d, u64 a, u64 b) {
    asm("fma.rn.f32x2 %0, %1, %2, %0;" : "+l"(d) : "l"(a), "l"(b));
}
__device__ __forceinline__ float2 unpack2(u64 v) {
    float2 r; asm("mov.b64 {%0, %1}, %2;" : "=f"(r.x), "=f"(r.y) : "l"(v)); return r;
}
__device__ __forceinline__ float tf32r(float v) {
    unsigned t; asm("cvt.rna.tf32.f32 %0, %1;" : "=r"(t) : "f"(v));
    return __uint_as_float(t);
}

// ---------------------------------------------------------------------------
// 1) inverse L2 norm per (b, hw)
// ---------------------------------------------------------------------------
__global__ void invnorm_kernel(const float* __restrict__ A, const float* __restrict__ B) {
    int t = blockIdx.x * blockDim.x + threadIdx.x;
    if (t >= 2 * BATCH * HW) return;
    const float* f = (t < BATCH * HW) ? A : B;
    float* o = (t < BATCH * HW) ? g_invnA : g_invnB;
    int idx = t % (BATCH * HW);
    int b = idx / HW, hw = idx % HW;
    const float* p = f + (size_t)b * CHANNELS * HW + hw;
    float s = 0.f;
#pragma unroll 16
    for (int c = 0; c < CHANNELS; ++c) {
        float v = p[(size_t)c * HW];
        s = fmaf(v, v, s);
    }
    o[idx] = rsqrtf(s + EPS_L2);
}

// ---------------------------------------------------------------------------
// 2) transpose + normalize + tf32-round into MMA-fragment layout
// ---------------------------------------------------------------------------
template <int MODE>
__global__ __launch_bounds__(256) void transnorm_kernel(
    const float* __restrict__ f, const float* __restrict__ invn,
    float* __restrict__ out) {
    __shared__ float sm[32][33];
    int b = blockIdx.z;
    int pb = blockIdx.x;
    int c0 = blockIdx.y * 32;
    int g0 = pb * 8;
    int hbase = (g0 / 24) * 2;
    int wbase = (g0 % 24) * 2;
    int tid = threadIdx.x;

    for (int idx = tid; idx < 1024; idx += 256) {
        int ci = idx >> 5, pos = idx & 31;
        int hh = pos >> 4, ww = pos & 15;
        int hw = (hbase + hh) * 48 + wbase + ww;
        float v = f[((size_t)b * CHANNELS + c0 + ci) * HW + hw] * invn[b * HW + hw];
        int p_in = ((ww >> 1) << 2) | (hh << 1) | (ww & 1);
        sm[p_in][ci] = tf32r(v);
    }
    __syncthreads();

    int p0 = pb * 32;
    if (MODE == 0) {
        int mt = tid >> 7, kt = (tid >> 5) & 3, lane = tid & 31;
        int rowin = lane >> 2, colin = lane & 3;
        float4 v;
        v.x = sm[mt * 16 + rowin][kt * 8 + colin];
        v.y = sm[mt * 16 + rowin + 8][kt * 8 + colin];
        v.z = sm[mt * 16 + rowin][kt * 8 + colin + 4];
        v.w = sm[mt * 16 + rowin + 8][kt * 8 + colin + 4];
        int rowblk = p0 >> 7;
        int mtile_g = ((p0 >> 4) & 7) + mt;
        int ktile_g = (c0 >> 3) + kt;
        size_t off = ((((size_t)b * 18 + rowblk) * 128 + ktile_g) * 8 + mtile_g) * 128
                     + lane * 4;
        *(float4*)(out + off) = v;
    } else {
        int colblk = p0 >> 7;
#pragma unroll
        for (int i = 0; i < 2; ++i) {
            int id = tid + i * 256;
            int nt = id >> 7, kt = (id >> 5) & 3, lane = id & 31;
            int rowin = lane >> 2, colin = lane & 3;
            float2 v;
            v.x = sm[nt * 8 + rowin][kt * 8 + colin];
            v.y = sm[nt * 8 + rowin][kt * 8 + colin + 4];
            int ntile_g = ((p0 >> 3) & 15) + nt;
            int ktile_g = (c0 >> 3) + kt;
            size_t off = ((((size_t)b * 18 + colblk) * 128 + ktile_g) * 16 + ntile_g) * 64
                         + lane * 2;
            *(float2*)(out + off) = v;
        }
    }
}

// ---------------------------------------------------------------------------
// 3) batched TF32 GEMM + fused 4x4 max-pool + relu/L2  (R8 config, frozen)
// ---------------------------------------------------------------------------
#define STAGE_FLOATS 4096   // 4 ktiles * 1024 floats

__global__ __launch_bounds__(128) void gemm_pool_kernel(
    const float* __restrict__ A, const float* __restrict__ B,
    float* __restrict__ out) {
    extern __shared__ char smem_raw[];
    float* As = (float*)smem_raw;            // [3][4096]
    float* Bs = As + 3 * STAGE_FLOATS;       // [3][4096]
    float* Cs = (float*)smem_raw;            // reused: [128][132]

    int b = blockIdx.z;
    const float* Ag = A + (size_t)b * HW * CHANNELS + (size_t)blockIdx.y * 128 * 1024;
    const float* Bg = B + (size_t)b * HW * CHANNELS + (size_t)blockIdx.x * 128 * 1024;

    int tid = threadIdx.x, lane = tid & 31, wid = tid >> 5;
    int wm = wid >> 1, wn = wid & 1;   // 2x2 warp grid, warp tile 64x64

    float acc[4][8][4];
#pragma unroll
    for (int i = 0; i < 4; ++i)
#pragma unroll
        for (int j = 0; j < 8; ++j)
#pragma unroll
            for (int k = 0; k < 4; ++k) acc[i][j][k] = 0.f;

    auto load_stage = [&](int s, int kt) {
        const float* ga = Ag + (size_t)kt * STAGE_FLOATS;
        const float* gb = Bg + (size_t)kt * STAGE_FLOATS;
#pragma unroll
        for (int i = 0; i < 8; ++i) {
            int idx = tid + i * 128;
            unsigned sa = smem_u32(As + s * STAGE_FLOATS + idx * 4);
            asm volatile("cp.async.cg.shared.global [%0], [%1], 16;\n" :: "r"(sa), "l"(ga + idx * 4));
            unsigned sb = smem_u32(Bs + s * STAGE_FLOATS + idx * 4);
            asm volatile("cp.async.cg.shared.global [%0], [%1], 16;\n" :: "r"(sb), "l"(gb + idx * 4));
        }
        asm volatile("cp.async.commit_group;\n");
    };

    const int KT = CHANNELS / 32;
    load_stage(0, 0);
    load_stage(1, 1);
    for (int kt = 0; kt < KT; ++kt) {
        if (kt + 2 < KT) {
            asm volatile("cp.async.wait_group 1;\n");
        } else {
            asm volatile("cp.async.wait_group 0;\n");
        }
        __syncthreads();
        if (kt + 2 < KT) load_stage((kt + 2) % 3, kt + 2);
        int cur = kt % 3;
        const float* Ab = As + cur * STAGE_FLOATS;
        const float* Bb = Bs + cur * STAGE_FLOATS;
#pragma unroll
        for (int kk = 0; kk < 4; ++kk) {
            uint2 bf[8];
#pragma unroll
            for (int ni = 0; ni < 8; ++ni)
                bf[ni] = *(const uint2*)(Bb + ((kk * 16 + wn * 8 + ni) * 32 + lane) * 2);
#pragma unroll
            for (int mi = 0; mi < 4; ++mi) {
                uint4 af = *(const uint4*)(Ab + ((kk * 8 + wm * 4 + mi) * 32 + lane) * 4);
#pragma unroll
                for (int ni = 0; ni < 8; ++ni) {
                    asm volatile(
                        "mma.sync.aligned.m16n8k8.row.col.f32.tf32.tf32.f32 "
                        "{%0,%1,%2,%3}, {%4,%5,%6,%7}, {%8,%9}, {%0,%1,%2,%3};\n"
                        : "+f"(acc[mi][ni][0]), "+f"(acc[mi][ni][1]),
                          "+f"(acc[mi][ni][2]), "+f"(acc[mi][ni][3])
                        : "r"(af.x), "r"(af.y), "r"(af.z), "r"(af.w),
                          "r"(bf[ni].x), "r"(bf[ni].y));
                }
            }
        }
    }
    __syncthreads();

#pragma unroll
    for (int mi = 0; mi < 4; ++mi) {
#pragma unroll
        for (int ni = 0; ni < 8; ++ni) {
            int r0 = wm * 64 + mi * 16 + (lane >> 2);
            int c0 = wn * 64 + ni * 8 + (lane & 3) * 2;
            Cs[r0 * 132 + c0]           = acc[mi][ni][0];
            Cs[r0 * 132 + c0 + 1]       = acc[mi][ni][1];
            Cs[(r0 + 8) * 132 + c0]     = acc[mi][ni][2];
            Cs[(r0 + 8) * 132 + c0 + 1] = acc[mi][ni][3];
        }
    }
    __syncthreads();

#pragma unroll
    for (int o = 0; o < 8; ++o) {
        int idx = tid * 8 + o;
        int pp = idx >> 5, qq = idx & 31;
        float m = -1e30f;
#pragma unroll
        for (int i = 0; i < 4; ++i)
#pragma unroll
            for (int j = 0; j < 4; ++j)
                m = fmaxf(m, Cs[(pp * 4 + i) * 132 + qq * 4 + j]);
        m = fmaxf(m, 0.f);
        float v = m * rsqrtf(m * m + EPS_L2);
        out[((size_t)b * POOL_P + blockIdx.y * 32 + pp) * POOL_P + blockIdx.x * 32 + qq] = v;
    }
}

// ---------------------------------------------------------------------------
// 4) row / col maxes -> reciprocals 1/(max+eps)
// ---------------------------------------------------------------------------
__global__ void rowmax_kernel(const float* __restrict__ X, float* __restrict__ amax) {
    int row = blockIdx.x, b = blockIdx.y;
    const float* p = X + ((size_t)b * POOL_P + row) * POOL_P;
    float m = 0.f;
    for (int q = threadIdx.x; q < POOL_P; q += 64) m = fmaxf(m, p[q]);
    __shared__ float red[64];
    red[threadIdx.x] = m;
    __syncthreads();
    if (threadIdx.x < 32) {
        m = fmaxf(red[threadIdx.x], red[threadIdx.x + 32]);
#pragma unroll
        for (int s = 16; s; s >>= 1) m = fmaxf(m, __shfl_down_sync(0xffffffffu, m, s));
        if (threadIdx.x == 0) amax[b * POOL_P + row] = 1.0f / (m + EPS_MM);
    }
}

__global__ void colmax_kernel(const float* __restrict__ X, float* __restrict__ bmax) {
    int q = blockIdx.x * 64 + threadIdx.x;
    int b = blockIdx.y;
    const float* p = X + (size_t)b * POOL_P * POOL_P + q;
    float m = 0.f;
#pragma unroll 8
    for (int r = 0; r < POOL_P; ++r) m = fmaxf(m, p[(size_t)r * POOL_P]);
    bmax[b * POOL_P + q] = 1.0f / (m + EPS_MM);
}

// ---------------------------------------------------------------------------
// 5) mutual matching: out = c * (c*ainv[p]) * (c*binv[q])
// ---------------------------------------------------------------------------
__global__ void mm_kernel(const float* __restrict__ X, const float* __restrict__ am,
                          const float* __restrict__ bm, float* __restrict__ O) {
    int i = blockIdx.x * blockDim.x + threadIdx.x;
    if (i >= POS_TOTAL) return;
    int q = i % POOL_P;
    int pr = (i / POOL_P) % POOL_P;
    int b = i / (POOL_P * POOL_P);
    float c = X[i];
    float r = c * am[b * POOL_P + pr];
    float s = c * bm[b * POOL_P + q];
    O[i] = c * r * s;
}

// ---------------------------------------------------------------------------
// 6) Conv4d FFMA2 v5 (conv2): page-based plane cache.
//    Per j1, load the 4 distinct y2-pages ONCE via cp.async (page-granular
//    commit groups); staged waits let pages 2,3 stream in under j2=0 compute.
//    Tap (j2, half) reads page j2+half. Traffic -33%, barriers 18 -> ~9.
// ---------------------------------------------------------------------------
#define RSTR 36              // plane row stride (floats)
#define CSTR (26 * RSTR)     // 936 floats per channel

template <int CIN, int COUT>
__global__ __launch_bounds__(288) void conv4d_v5_kernel(
    const float* __restrict__ in, const float* __restrict__ w,
    const float* __restrict__ bias, float* __restrict__ out) {
    constexpr int CP2 = (COUT + 1) & ~1;
    constexpr int COP = CP2 / 2;
    constexpr int WPAD = (CIN * 81 * CP2 + 3) & ~3;
    constexpr int PAGE = CIN * CSTR;
    extern __shared__ float sm[];
    float* wsm = sm;
    float* pl = sm + WPAD;              // [4 pages][PAGE]

    int tid = threadIdx.x;
    int b = blockIdx.z, x1 = blockIdx.y, bx = blockIdx.x;
    int half = tid / 144, u = tid % 144;
    int x3 = 2 * (u / 12), x4 = 2 * (u % 12);
    int x2 = bx * 2 + half;

    for (int i = tid; i < CIN * 81 * CP2; i += 288) {
        int co = i % CP2;
        int rest = i / CP2;
        int ci = rest / 81, tap = rest % 81;
        wsm[i] = (co < COUT) ? w[(co * CIN + ci) * 81 + tap] : 0.f;
    }
    // static halo zeroing for all 4 pages (rows 0,25; cols 3,28)
    for (int i = tid; i < 4 * CIN * 26; i += 288) {
        int p = i / (CIN * 26), r = i % (CIN * 26);
        int ci = r / 26, rr = r % 26;
        float* rowp = pl + p * PAGE + ci * CSTR + rr * RSTR;
        if (rr == 0 || rr == 25) {
            for (int c = 3; c <= 28; ++c) rowp[c] = 0.f;
        } else {
            rowp[3] = 0.f; rowp[28] = 0.f;
        }
    }

    u64 acc[COP][4];
#pragma unroll
    for (int cp = 0; cp < COP; ++cp)
#pragma unroll
        for (int o = 0; o < 4; ++o) acc[cp][o] = 0ull;

    auto compute_tap = [&](int j1, int j2) {
        const float* base = pl + (j2 + half) * PAGE;
        for (int ci = 0; ci < CIN; ++ci) {
#pragma unroll
            for (int j3 = 0; j3 < 3; ++j3) {
                const float* r0 = base + ci * CSTR + (x3 + j3) * RSTR + 3 + x4;
                const float* r1 = r0 + RSTR;
                u64 vd0[4], vd1[4];
#pragma unroll
                for (int t = 0; t < 4; ++t) {
                    float a = r0[t]; vd0[t] = pack2(a, a);
                    float c2 = r1[t]; vd1[t] = pack2(c2, c2);
                }
                const float* wb = wsm + (ci * 81 + j1 * 27 + j2 * 9 + j3 * 3) * CP2;
#pragma unroll
                for (int j4 = 0; j4 < 3; ++j4) {
#pragma unroll
                    for (int cp = 0; cp < COP; ++cp) {
                        u64 wp = *reinterpret_cast<const u64*>(wb + j4 * CP2 + cp * 2);
                        fma2(acc[cp][0], wp, vd0[j4]);
                        fma2(acc[cp][1], wp, vd0[j4 + 1]);
                        fma2(acc[cp][2], wp, vd1[j4]);
                        fma2(acc[cp][3], wp, vd1[j4 + 1]);
                    }
                }
            }
        }
    };

    for (int j1 = 0; j1 < 3; ++j1) {
        int y1 = x1 + j1 - 1;
        if ((unsigned)y1 >= 24u) continue;   // CTA-uniform: zero contribution
        __syncthreads();                     // previous j1's pages consumed
#pragma unroll
        for (int p = 0; p < 4; ++p) {
            int y2 = bx * 2 + p - 1;
            bool pv = (unsigned)y2 < 24u;
            for (int t = tid; t < CIN * 24; t += 288) {
                int ci = t / 24, rr = 1 + t % 24;
                float* dst = pl + p * PAGE + ci * CSTR + rr * RSTR + 4;
                if (pv) {
                    const float* src = in + ((((size_t)b * CIN + ci) * 24 + y1) * 24 + y2)
                                           * POOL_P + (rr - 1) * 24;
                    unsigned d = smem_u32(dst);
#pragma unroll
                    for (int c = 0; c < 6; ++c)
                        asm volatile("cp.async.cg.shared.global [%0], [%1], 16;\n"
                                     :: "r"(d + c * 16), "l"(src + c * 4));
                } else {
                    float4 z = make_float4(0.f, 0.f, 0.f, 0.f);
#pragma unroll
                    for (int c = 0; c < 6; ++c) *(float4*)(dst + c * 4) = z;
                }
            }
            asm volatile("cp.async.commit_group;\n");
        }
        asm volatile("cp.async.wait_group 2;\n");   // pages 0,1 ready
        __syncthreads();
        compute_tap(j1, 0);
        asm volatile("cp.async.wait_group 1;\n");   // page 2 ready
        __syncthreads();
        compute_tap(j1, 1);
        asm volatile("cp.async.wait_group 0;\n");   // page 3 ready
        __syncthreads();
        compute_tap(j1, 2);
    }

    int pos0 = x3 * 24 + x4;
#pragma unroll
    for (int cp = 0; cp < COP; ++cp) {
        int co0 = 2 * cp, co1 = co0 + 1;
        float2 q0 = unpack2(acc[cp][0]);
        float2 q1 = unpack2(acc[cp][1]);
        float2 q2 = unpack2(acc[cp][2]);
        float2 q3 = unpack2(acc[cp][3]);
        float b0 = bias[co0];
        size_t base0 = ((((size_t)b * COUT + co0) * 24 + x1) * 24 + x2) * POOL_P + pos0;
        *(float2*)(out + base0)      = make_float2(fmaxf(q0.x + b0, 0.f), fmaxf(q1.x + b0, 0.f));
        *(float2*)(out + base0 + 24) = make_float2(fmaxf(q2.x + b0, 0.f), fmaxf(q3.x + b0, 0.f));
        if (co1 < COUT) {
            float b1 = bias[co1];
            size_t base1 = ((((size_t)b * COUT + co1) * 24 + x1) * 24 + x2) * POOL_P + pos0;
            *(float2*)(out + base1)      = make_float2(fmaxf(q0.y + b1, 0.f), fmaxf(q1.y + b1, 0.f));
            *(float2*)(out + base1 + 24) = make_float2(fmaxf(q2.y + b1, 0.f), fmaxf(q3.y + b1, 0.f));
        }
    }
}

// ---------------------------------------------------------------------------
// 6a) Conv1 (CIN=1): preload ALL 12 distinct haloed planes once (from R10).
// ---------------------------------------------------------------------------
template <int COUT>
__global__ __launch_bounds__(288) void conv4d_cin1_kernel(
    const float* __restrict__ in, const float* __restrict__ w,
    const float* __restrict__ bias, float* __restrict__ out) {
    constexpr int CP2 = (COUT + 1) & ~1;
    constexpr int COP = CP2 / 2;
    constexpr int WPAD = (81 * CP2 + 3) & ~3;
    extern __shared__ float sm[];
    float* wsm = sm;                    // [81][CP2]
    float* pl = sm + WPAD;              // [12][CSTR]

    int tid = threadIdx.x;
    int b = blockIdx.z, x1 = blockIdx.y, bx = blockIdx.x;
    int half = tid / 144, u = tid % 144;
    int x3 = 2 * (u / 12), x4 = 2 * (u % 12);
    int x2 = bx * 2 + half;

    for (int i = tid; i < 81 * CP2; i += 288) {
        int co = i % CP2, tap = i / CP2;
        wsm[i] = (co < COUT) ? w[co * 81 + tap] : 0.f;
    }
    for (int i = tid; i < 12 * 26; i += 288) {
        int p = i / 26, rr = i % 26;
        float* rowp = pl + p * CSTR + rr * RSTR;
        if (rr == 0 || rr == 25) {
            for (int c = 3; c <= 28; ++c) rowp[c] = 0.f;
        } else {
            rowp[3] = 0.f; rowp[28] = 0.f;
        }
    }
    {
        int p = tid / 24, rr = 1 + tid % 24;
        int y1 = x1 + (p >> 2) - 1;
        int y2 = bx * 2 + (p & 3) - 1;
        float* dst = pl + p * CSTR + rr * RSTR + 4;
        if ((unsigned)y1 < 24u && (unsigned)y2 < 24u) {
            const float* src = in + (((size_t)b * 24 + y1) * 24 + y2) * POOL_P + (rr - 1) * 24;
#pragma unroll
            for (int c = 0; c < 6; ++c)
                *(float4*)(dst + c * 4) = *(const float4*)(src + c * 4);
        } else {
            float4 z = make_float4(0.f, 0.f, 0.f, 0.f);
#pragma unroll
            for (int c = 0; c < 6; ++c) *(float4*)(dst + c * 4) = z;
        }
    }
    __syncthreads();

    u64 acc[COP][4];
#pragma unroll
    for (int cp = 0; cp < COP; ++cp)
#pragma unroll
        for (int o = 0; o < 4; ++o) acc[cp][o] = 0ull;

#pragma unroll
    for (int g = 0; g < 9; ++g) {
        int j1 = g / 3, j2 = g % 3;
        const float* base = pl + (j1 * 4 + j2 + half) * CSTR;
#pragma unroll
        for (int j3 = 0; j3 < 3; ++j3) {
            const float* r0 = base + (x3 + j3) * RSTR + 3 + x4;
            const float* r1 = r0 + RSTR;
            u64 vd0[4], vd1[4];
#pragma unroll
            for (int t = 0; t < 4; ++t) {
                float a = r0[t]; vd0[t] = pack2(a, a);
                float c2 = r1[t]; vd1[t] = pack2(c2, c2);
            }
            const float* wb = wsm + (j1 * 27 + j2 * 9 + j3 * 3) * CP2;
#pragma unroll
            for (int j4 = 0; j4 < 3; ++j4) {
#pragma unroll
                for (int cp = 0; cp < COP; ++cp) {
                    u64 wp = *reinterpret_cast<const u64*>(wb + j4 * CP2 + cp * 2);
                    fma2(acc[cp][0], wp, vd0[j4]);
                    fma2(acc[cp][1], wp, vd0[j4 + 1]);
                    fma2(acc[cp][2], wp, vd1[j4]);
                    fma2(acc[cp][3], wp, vd1[j4 + 1]);
                }
            }
        }
    }

    int pos0 = x3 * 24 + x4;
#pragma unroll
    for (int cp = 0; cp < COP; ++cp) {
        int co0 = 2 * cp, co1 = co0 + 1;
        float2 q0 = unpack2(acc[cp][0]);
        float2 q1 = unpack2(acc[cp][1]);
        float2 q2 = unpack2(acc[cp][2]);
        float2 q3 = unpack2(acc[cp][3]);
        float b0 = bias[co0];
        size_t base0 = ((((size_t)b * COUT + co0) * 24 + x1) * 24 + x2) * POOL_P + pos0;
        *(float2*)(out + base0)      = make_float2(fmaxf(q0.x + b0, 0.f), fmaxf(q1.x + b0, 0.f));
        *(float2*)(out + base0 + 24) = make_float2(fmaxf(q2.x + b0, 0.f), fmaxf(q3.x + b0, 0.f));
        if (co1 < COUT) {
            float b1 = bias[co1];
            size_t base1 = ((((size_t)b * COUT + co1) * 24 + x1) * 24 + x2) * POOL_P + pos0;
            *(float2*)(out + base1)      = make_float2(fmaxf(q0.y + b1, 0.f), fmaxf(q1.y + b1, 0.f));
            *(float2*)(out + base1 + 24) = make_float2(fmaxf(q2.y + b1, 0.f), fmaxf(q3.y + b1, 0.f));
        }
    }
}

// ---------------------------------------------------------------------------
// 6b) Conv3 (COUT=1): row-pair f32x2 + the same page-based plane cache.
// ---------------------------------------------------------------------------
template <int CIN>
__global__ __launch_bounds__(288) void conv4d_c1v5_kernel(
    const float* __restrict__ in, const float* __restrict__ w,
    const float* __restrict__ bias, float* __restrict__ out) {
    constexpr int WPAD = (2 * CIN * 81 + 3) & ~3;
    constexpr int PAGE = CIN * CSTR;
    extern __shared__ float sm[];
    float* wsm = sm;                    // duplicated (w,w) pairs
    float* pl = sm + WPAD;              // [4 pages][PAGE]

    int tid = threadIdx.x;
    int b = blockIdx.z, x1 = blockIdx.y, bx = blockIdx.x;
    int half = tid / 144, u = tid % 144;
    int x3 = 2 * (u / 12), x4 = 2 * (u % 12);
    int x2 = bx * 2 + half;

    for (int i = tid; i < CIN * 81; i += 288) {
        float v = w[i];
        wsm[2 * i] = v; wsm[2 * i + 1] = v;
    }
    for (int i = tid; i < 4 * CIN * 26; i += 288) {
        int p = i / (CIN * 26), r = i % (CIN * 26);
        int ci = r / 26, rr = r % 26;
        float* rowp = pl + p * PAGE + ci * CSTR + rr * RSTR;
        if (rr == 0 || rr == 25) {
            for (int c = 3; c <= 28; ++c) rowp[c] = 0.f;
        } else {
            rowp[3] = 0.f; rowp[28] = 0.f;
        }
    }

    u64 acc[2] = {0ull, 0ull};

    auto compute_tap = [&](int j1, int j2) {
        const float* base = pl + (j2 + half) * PAGE;
        for (int ci = 0; ci < CIN; ++ci) {
#pragma unroll
            for (int j3 = 0; j3 < 3; ++j3) {
                const float* r0 = base + ci * CSTR + (x3 + j3) * RSTR + 3 + x4;
                const float* r1 = r0 + RSTR;
                u64 vd[4];
#pragma unroll
                for (int t = 0; t < 4; ++t) vd[t] = pack2(r0[t], r1[t]);
                const u64* wb = reinterpret_cast<const u64*>(
                    wsm + 2 * (ci * 81 + j1 * 27 + j2 * 9 + j3 * 3));
#pragma unroll
                for (int j4 = 0; j4 < 3; ++j4) {
                    u64 wp = wb[j4];
                    fma2(acc[0], wp, vd[j4]);
                    fma2(acc[1], wp, vd[j4 + 1]);
                }
            }
        }
    };

    for (int j1 = 0; j1 < 3; ++j1) {
        int y1 = x1 + j1 - 1;
        if ((unsigned)y1 >= 24u) continue;
        __syncthreads();
#pragma unroll
        for (int p = 0; p < 4; ++p) {
            int y2 = bx * 2 + p - 1;
            bool pv = (unsigned)y2 < 24u;
            for (int t = tid; t < CIN * 24; t += 288) {
                int ci = t / 24, rr = 1 + t % 24;
                float* dst = pl + p * PAGE + ci * CSTR + rr * RSTR + 4;
                if (pv) {
                    const float* src = in + ((((size_t)b * CIN + ci) * 24 + y1) * 24 + y2)
                                           * POOL_P + (rr - 1) * 24;
                    unsigned d = smem_u32(dst);
#pragma unroll
                    for (int c = 0; c < 6; ++c)
                        asm volatile("cp.async.cg.shared.global [%0], [%1], 16;\n"
                                     :: "r"(d + c * 16), "l"(src + c * 4));
                } else {
                    float4 z = make_float4(0.f, 0.f, 0.f, 0.f);
#pragma unroll
                    for (int c = 0; c < 6; ++c) *(float4*)(dst + c * 4) = z;
                }
            }
            asm volatile("cp.async.commit_group;\n");
        }
        asm volatile("cp.async.wait_group 2;\n");
        __syncthreads();
        compute_tap(j1, 0);
        asm volatile("cp.async.wait_group 1;\n");
        __syncthreads();
        compute_tap(j1, 1);
        asm volatile("cp.async.wait_group 0;\n");
        __syncthreads();
        compute_tap(j1, 2);
    }

    float b0 = bias[0];
    float2 c0 = unpack2(acc[0]);
    float2 c1 = unpack2(acc[1]);
    size_t base0 = (((size_t)b * 24 + x1) * 24 + x2) * POOL_P + x3 * 24 + x4;
    *(float2*)(out + base0)      = make_float2(fmaxf(c0.x + b0, 0.f), fmaxf(c1.x + b0, 0.f));
    *(float2*)(out + base0 + 24) = make_float2(fmaxf(c0.y + b0, 0.f), fmaxf(c1.y + b0, 0.f));
}

// host-side smem mirrors
static inline size_t conv_v5_smem_bytes(int cin, int cout) {
    int cp2 = (cout + 1) & ~1;
    size_t wpad = ((size_t)cin * 81 * cp2 + 3) & ~(size_t)3;
    return (wpad + 4 * (size_t)cin * CSTR) * 4;
}
static inline size_t conv_cin1_smem_bytes(int cout) {
    int cp2 = (cout + 1) & ~1;
    size_t wpad = ((size_t)81 * cp2 + 3) & ~(size_t)3;
    return (wpad + 12 * (size_t)CSTR) * 4;
}
static inline size_t conv_c1v5_smem_bytes(int cin) {
    size_t wpad = (2 * (size_t)cin * 81 + 3) & ~(size_t)3;
    return (wpad + 4 * (size_t)cin * CSTR) * 4;
}

// ---------------------------------------------------------------------------
// Launch
// ---------------------------------------------------------------------------
extern "C" void kernel_launch(void* const* d_in, const int* in_sizes, int n_in,
                              void* d_out, int out_size) {
    const float* fA = (const float*)d_in[0];
    const float* fB = (const float*)d_in[1];
    const float* w1 = (const float*)d_in[2];
    const float* b1 = (const float*)d_in[3];
    const float* w2 = (const float*)d_in[4];
    const float* b2 = (const float*)d_in[5];
    const float* w3 = (const float*)d_in[6];
    const float* b3 = (const float*)d_in[7];
    float* out = (float*)d_out;

    float *gA, *gB, *invA, *invB, *cpool, *x1b, *x2b, *amax, *bmax;
    cudaGetSymbolAddress((void**)&gA, g_A);
    cudaGetSymbolAddress((void**)&gB, g_B);
    cudaGetSymbolAddress((void**)&invA, g_invnA);
    cudaGetSymbolAddress((void**)&invB, g_invnB);
    cudaGetSymbolAddress((void**)&cpool, g_cpool);
    cudaGetSymbolAddress((void**)&x1b, g_x1);
    cudaGetSymbolAddress((void**)&x2b, g_x2);
    cudaGetSymbolAddress((void**)&amax, g_amax);
    cudaGetSymbolAddress((void**)&bmax, g_bmax);

    size_t sm1 = conv_cin1_smem_bytes(10);    // ~48.2 KB
    size_t sm2 = conv_v5_smem_bytes(10, 10);  // ~182.2 KB (1 CTA/SM)
    size_t sm3 = conv_c1v5_smem_bytes(10);    // ~156.2 KB (1 CTA/SM)
    size_t smg = 3 * 2 * STAGE_FLOATS * 4;    // 96 KB

    cudaFuncSetAttribute(gemm_pool_kernel, cudaFuncAttributeMaxDynamicSharedMemorySize, (int)smg);
    cudaFuncSetAttribute(conv4d_cin1_kernel<10>, cudaFuncAttributeMaxDynamicSharedMemorySize, (int)sm1);
    cudaFuncSetAttribute(conv4d_v5_kernel<10, 10>, cudaFuncAttributeMaxDynamicSharedMemorySize, (int)sm2);
    cudaFuncSetAttribute(conv4d_c1v5_kernel<10>, cudaFuncAttributeMaxDynamicSharedMemorySize, (int)sm3);

    // 1) inverse norms
    invnorm_kernel<<<(2 * BATCH * HW) / 256, 256>>>(fA, fB);

    // 2) transpose + normalize + tf32 round into fragment-ordered layouts
    dim3 tgrid(72, 32, BATCH);
    transnorm_kernel<0><<<tgrid, 256>>>(fA, invA, gA);
    transnorm_kernel<1><<<tgrid, 256>>>(fB, invB, gB);

    // 3) TF32 GEMM + pool + relu/L2
    gemm_pool_kernel<<<dim3(18, 18, BATCH), 128, smg>>>(gA, gB, cpool);

    // 4) mutual matching #1 (in place)
    rowmax_kernel<<<dim3(POOL_P, BATCH), 64>>>(cpool, amax);
    colmax_kernel<<<dim3(POOL_P / 64, BATCH), 64>>>(cpool, bmax);
    mm_kernel<<<(POS_TOTAL + 255) / 256, 256>>>(cpool, amax, bmax, cpool);

    // 5) neighbourhood consensus convs
    dim3 cgrid(12, 24, BATCH);
    conv4d_cin1_kernel<10><<<cgrid, 288, sm1>>>(cpool, w1, b1, x1b);
    conv4d_v5_kernel<10, 10><<<cgrid, 288, sm2>>>(x1b, w2, b2, x2b);
    conv4d_c1v5_kernel<10><<<cgrid, 288, sm3>>>(x2b, w3, b3, cpool);

    // 6) mutual matching #2 -> output
    rowmax_kernel<<<dim3(POOL_P, BATCH), 64>>>(cpool, amax);
    colmax_kernel<<<dim3(POOL_P / 64, BATCH), 64>>>(cpool, bmax);
    mm_kernel<<<(POS_TOTAL + 255) / 256, 256>>>(cpool, amax, bmax, out);

    (void)in_sizes; (void)n_in; (void)out_size;
}

// round 12
// speedup vs baseline: 1.7628x; 1.7628x over previous
#include <cuda_runtime.h>
#include <cuda_bf16.h>

// ---------------------------------------------------------------------------
// Problem constants
// ---------------------------------------------------------------------------
#define BATCH 8
#define CHANNELS 1024
#define HW 2304           // 48*48
#define POOL_P 576        // 24*24
#define POS_TOTAL (BATCH*POOL_P*POOL_P)   // 2,654,208
#define EPS_L2 1e-6f
#define EPS_MM 1e-5f

typedef unsigned long long u64;

// ---------------------------------------------------------------------------
// Scratch (device globals; no allocation allowed)
// ---------------------------------------------------------------------------
__device__ float g_A[BATCH * HW * CHANNELS];
__device__ float g_B[BATCH * HW * CHANNELS];
__device__ float g_invnA[BATCH * HW];
__device__ float g_invnB[BATCH * HW];
__device__ float g_cpool[POS_TOTAL];
__device__ float g_x1[BATCH * 10 * POOL_P * POOL_P];
__device__ float g_x2[BATCH * 10 * POOL_P * POOL_P];
__device__ float g_amax[BATCH * POOL_P];      // reciprocals 1/(max+eps)
__device__ float g_bmax[BATCH * POOL_P];

// ---------------------------------------------------------------------------
// Helpers
// ---------------------------------------------------------------------------
__device__ __forceinline__ unsigned smem_u32(const void* p) {
    return (unsigned)__cvta_generic_to_shared(p);
}
__device__ __forceinline__ u64 pack2(float a, float b) {
    u64 r; asm("mov.b64 %0, {%1, %2};" : "=l"(r) : "f"(a), "f"(b)); return r;
}
__device__ __forceinline__ void fma2(u64& d, u64 a, u64 b) {
    asm("fma.rn.f32x2 %0, %1, %2, %0;" : "+l"(d) : "l"(a), "l"(b));
}
__device__ __forceinline__ float2 unpack2(u64 v) {
    float2 r; asm("mov.b64 {%0, %1}, %2;" : "=f"(r.x), "=f"(r.y) : "l"(v)); return r;
}
__device__ __forceinline__ float tf32r(float v) {
    unsigned t; asm("cvt.rna.tf32.f32 %0, %1;" : "=r"(t) : "f"(v));
    return __uint_as_float(t);
}

// ---------------------------------------------------------------------------
// 1) inverse L2 norm per (b, hw)
// ---------------------------------------------------------------------------
__global__ void invnorm_kernel(const float* __restrict__ A, const float* __restrict__ B) {
    int t = blockIdx.x * blockDim.x + threadIdx.x;
    if (t >= 2 * BATCH * HW) return;
    const float* f = (t < BATCH * HW) ? A : B;
    float* o = (t < BATCH * HW) ? g_invnA : g_invnB;
    int idx = t % (BATCH * HW);
    int b = idx / HW, hw = idx % HW;
    const float* p = f + (size_t)b * CHANNELS * HW + hw;
    float s = 0.f;
#pragma unroll 16
    for (int c = 0; c < CHANNELS; ++c) {
        float v = p[(size_t)c * HW];
        s = fmaf(v, v, s);
    }
    o[idx] = rsqrtf(s + EPS_L2);
}

// ---------------------------------------------------------------------------
// 2) transpose + normalize + tf32-round into MMA-fragment layout.
//    Single launch: grid.z = 16; z<8 -> A-side (MODE0), z>=8 -> B-side (MODE1).
// ---------------------------------------------------------------------------
__global__ __launch_bounds__(256) void transnorm_kernel(
    const float* __restrict__ fA, const float* __restrict__ fB,
    const float* __restrict__ invA, const float* __restrict__ invB,
    float* __restrict__ outA, float* __restrict__ outB) {
    __shared__ float sm[32][33];
    int zz = blockIdx.z;
    int mode = zz >> 3;
    int b = zz & 7;
    const float* f = mode ? fB : fA;
    const float* invn = mode ? invB : invA;
    float* out = mode ? outB : outA;

    int pb = blockIdx.x;
    int c0 = blockIdx.y * 32;
    int g0 = pb * 8;
    int hbase = (g0 / 24) * 2;
    int wbase = (g0 % 24) * 2;
    int tid = threadIdx.x;

    for (int idx = tid; idx < 1024; idx += 256) {
        int ci = idx >> 5, pos = idx & 31;
        int hh = pos >> 4, ww = pos & 15;
        int hw = (hbase + hh) * 48 + wbase + ww;
        float v = f[((size_t)b * CHANNELS + c0 + ci) * HW + hw] * invn[b * HW + hw];
        int p_in = ((ww >> 1) << 2) | (hh << 1) | (ww & 1);
        sm[p_in][ci] = tf32r(v);
    }
    __syncthreads();

    int p0 = pb * 32;
    if (mode == 0) {
        int mt = tid >> 7, kt = (tid >> 5) & 3, lane = tid & 31;
        int rowin = lane >> 2, colin = lane & 3;
        float4 v;
        v.x = sm[mt * 16 + rowin][kt * 8 + colin];
        v.y = sm[mt * 16 + rowin + 8][kt * 8 + colin];
        v.z = sm[mt * 16 + rowin][kt * 8 + colin + 4];
        v.w = sm[mt * 16 + rowin + 8][kt * 8 + colin + 4];
        int rowblk = p0 >> 7;
        int mtile_g = ((p0 >> 4) & 7) + mt;
        int ktile_g = (c0 >> 3) + kt;
        size_t off = ((((size_t)b * 18 + rowblk) * 128 + ktile_g) * 8 + mtile_g) * 128
                     + lane * 4;
        *(float4*)(out + off) = v;
    } else {
        int colblk = p0 >> 7;
#pragma unroll
        for (int i = 0; i < 2; ++i) {
            int id = tid + i * 256;
            int nt = id >> 7, kt = (id >> 5) & 3, lane = id & 31;
            int rowin = lane >> 2, colin = lane & 3;
            float2 v;
            v.x = sm[nt * 8 + rowin][kt * 8 + colin];
            v.y = sm[nt * 8 + rowin][kt * 8 + colin + 4];
            int ntile_g = ((p0 >> 3) & 15) + nt;
            int ktile_g = (c0 >> 3) + kt;
            size_t off = ((((size_t)b * 18 + colblk) * 128 + ktile_g) * 16 + ntile_g) * 64
                         + lane * 2;
            *(float2*)(out + off) = v;
        }
    }
}

// ---------------------------------------------------------------------------
// 3) batched TF32 GEMM + fused 4x4 max-pool + relu/L2  (R8 config, frozen)
// ---------------------------------------------------------------------------
#define STAGE_FLOATS 4096   // 4 ktiles * 1024 floats

__global__ __launch_bounds__(128) void gemm_pool_kernel(
    const float* __restrict__ A, const float* __restrict__ B,
    float* __restrict__ out) {
    extern __shared__ char smem_raw[];
    float* As = (float*)smem_raw;            // [3][4096]
    float* Bs = As + 3 * STAGE_FLOATS;       // [3][4096]
    float* Cs = (float*)smem_raw;            // reused: [128][132]

    int b = blockIdx.z;
    const float* Ag = A + (size_t)b * HW * CHANNELS + (size_t)blockIdx.y * 128 * 1024;
    const float* Bg = B + (size_t)b * HW * CHANNELS + (size_t)blockIdx.x * 128 * 1024;

    int tid = threadIdx.x, lane = tid & 31, wid = tid >> 5;
    int wm = wid >> 1, wn = wid & 1;   // 2x2 warp grid, warp tile 64x64

    float acc[4][8][4];
#pragma unroll
    for (int i = 0; i < 4; ++i)
#pragma unroll
        for (int j = 0; j < 8; ++j)
#pragma unroll
            for (int k = 0; k < 4; ++k) acc[i][j][k] = 0.f;

    auto load_stage = [&](int s, int kt) {
        const float* ga = Ag + (size_t)kt * STAGE_FLOATS;
        const float* gb = Bg + (size_t)kt * STAGE_FLOATS;
#pragma unroll
        for (int i = 0; i < 8; ++i) {
            int idx = tid + i * 128;
            unsigned sa = smem_u32(As + s * STAGE_FLOATS + idx * 4);
            asm volatile("cp.async.cg.shared.global [%0], [%1], 16;\n" :: "r"(sa), "l"(ga + idx * 4));
            unsigned sb = smem_u32(Bs + s * STAGE_FLOATS + idx * 4);
            asm volatile("cp.async.cg.shared.global [%0], [%1], 16;\n" :: "r"(sb), "l"(gb + idx * 4));
        }
        asm volatile("cp.async.commit_group;\n");
    };

    const int KT = CHANNELS / 32;
    load_stage(0, 0);
    load_stage(1, 1);
    for (int kt = 0; kt < KT; ++kt) {
        if (kt + 2 < KT) {
            asm volatile("cp.async.wait_group 1;\n");
        } else {
            asm volatile("cp.async.wait_group 0;\n");
        }
        __syncthreads();
        if (kt + 2 < KT) load_stage((kt + 2) % 3, kt + 2);
        int cur = kt % 3;
        const float* Ab = As + cur * STAGE_FLOATS;
        const float* Bb = Bs + cur * STAGE_FLOATS;
#pragma unroll
        for (int kk = 0; kk < 4; ++kk) {
            uint2 bf[8];
#pragma unroll
            for (int ni = 0; ni < 8; ++ni)
                bf[ni] = *(const uint2*)(Bb + ((kk * 16 + wn * 8 + ni) * 32 + lane) * 2);
#pragma unroll
            for (int mi = 0; mi < 4; ++mi) {
                uint4 af = *(const uint4*)(Ab + ((kk * 8 + wm * 4 + mi) * 32 + lane) * 4);
#pragma unroll
                for (int ni = 0; ni < 8; ++ni) {
                    asm volatile(
                        "mma.sync.aligned.m16n8k8.row.col.f32.tf32.tf32.f32 "
                        "{%0,%1,%2,%3}, {%4,%5,%6,%7}, {%8,%9}, {%0,%1,%2,%3};\n"
                        : "+f"(acc[mi][ni][0]), "+f"(acc[mi][ni][1]),
                          "+f"(acc[mi][ni][2]), "+f"(acc[mi][ni][3])
                        : "r"(af.x), "r"(af.y), "r"(af.z), "r"(af.w),
                          "r"(bf[ni].x), "r"(bf[ni].y));
                }
            }
        }
    }
    __syncthreads();

#pragma unroll
    for (int mi = 0; mi < 4; ++mi) {
#pragma unroll
        for (int ni = 0; ni < 8; ++ni) {
            int r0 = wm * 64 + mi * 16 + (lane >> 2);
            int c0 = wn * 64 + ni * 8 + (lane & 3) * 2;
            Cs[r0 * 132 + c0]           = acc[mi][ni][0];
            Cs[r0 * 132 + c0 + 1]       = acc[mi][ni][1];
            Cs[(r0 + 8) * 132 + c0]     = acc[mi][ni][2];
            Cs[(r0 + 8) * 132 + c0 + 1] = acc[mi][ni][3];
        }
    }
    __syncthreads();

#pragma unroll
    for (int o = 0; o < 8; ++o) {
        int idx = tid * 8 + o;
        int pp = idx >> 5, qq = idx & 31;
        float m = -1e30f;
#pragma unroll
        for (int i = 0; i < 4; ++i)
#pragma unroll
            for (int j = 0; j < 4; ++j)
                m = fmaxf(m, Cs[(pp * 4 + i) * 132 + qq * 4 + j]);
        m = fmaxf(m, 0.f);
        float v = m * rsqrtf(m * m + EPS_L2);
        out[((size_t)b * POOL_P + blockIdx.y * 32 + pp) * POOL_P + blockIdx.x * 32 + qq] = v;
    }
}

// ---------------------------------------------------------------------------
// 4) row + col maxes in ONE launch -> reciprocals 1/(max+eps).
//    blockIdx.x < 576: row max; else: 64-column strip of col max.
// ---------------------------------------------------------------------------
__global__ void rowcolmax_kernel(const float* __restrict__ X,
                                 float* __restrict__ amax, float* __restrict__ bmax) {
    int b = blockIdx.y;
    if (blockIdx.x < POOL_P) {
        int row = blockIdx.x;
        const float* p = X + ((size_t)b * POOL_P + row) * POOL_P;
        float m = 0.f;
        for (int q = threadIdx.x; q < POOL_P; q += 64) m = fmaxf(m, p[q]);
        __shared__ float red[64];
        red[threadIdx.x] = m;
        __syncthreads();
        if (threadIdx.x < 32) {
            m = fmaxf(red[threadIdx.x], red[threadIdx.x + 32]);
#pragma unroll
            for (int s = 16; s; s >>= 1) m = fmaxf(m, __shfl_down_sync(0xffffffffu, m, s));
            if (threadIdx.x == 0) amax[b * POOL_P + row] = 1.0f / (m + EPS_MM);
        }
    } else {
        int q = (blockIdx.x - POOL_P) * 64 + threadIdx.x;
        const float* p = X + (size_t)b * POOL_P * POOL_P + q;
        float m = 0.f;
#pragma unroll 8
        for (int r = 0; r < POOL_P; ++r) m = fmaxf(m, p[(size_t)r * POOL_P]);
        bmax[b * POOL_P + q] = 1.0f / (m + EPS_MM);
    }
}

// ---------------------------------------------------------------------------
// 5) mutual matching: out = c * (c*ainv[p]) * (c*binv[q])
// ---------------------------------------------------------------------------
__global__ void mm_kernel(const float* __restrict__ X, const float* __restrict__ am,
                          const float* __restrict__ bm, float* __restrict__ O) {
    int i = blockIdx.x * blockDim.x + threadIdx.x;
    if (i >= POS_TOTAL) return;
    int q = i % POOL_P;
    int pr = (i / POOL_P) % POOL_P;
    int b = i / (POOL_P * POOL_P);
    float c = X[i];
    float r = c * am[b * POOL_P + pr];
    float s = c * bm[b * POOL_P + q];
    O[i] = c * r * s;
}

// ---------------------------------------------------------------------------
// 6) Conv4d FFMA2 v4 (conv2): 288 thr = 2 x2-planes x 144; 2x2 tile/thread.
//    j1 taps with invalid y1 are skipped CTA-uniformly (strictly less work).
// ---------------------------------------------------------------------------
#define RSTR 36              // plane row stride (floats)
#define CSTR (26 * RSTR)     // 936 floats per channel

template <int CIN, int COUT>
__global__ __launch_bounds__(288) void conv4d_v4_kernel(
    const float* __restrict__ in, const float* __restrict__ w,
    const float* __restrict__ bias, float* __restrict__ out) {
    constexpr int CP2 = (COUT + 1) & ~1;
    constexpr int COP = CP2 / 2;
    constexpr int WPAD = (CIN * 81 * CP2 + 3) & ~3;
    constexpr int PLN = CIN * CSTR;
    extern __shared__ float sm[];
    float* wsm = sm;
    float* pl = sm + WPAD;

    int tid = threadIdx.x;
    int b = blockIdx.z, x1 = blockIdx.y, bx = blockIdx.x;
    int half = tid / 144, u = tid % 144;
    int x3 = 2 * (u / 12), x4 = 2 * (u % 12);
    int x2 = bx * 2 + half;

    for (int i = tid; i < CIN * 81 * CP2; i += 288) {
        int co = i % CP2;
        int rest = i / CP2;
        int ci = rest / 81, tap = rest % 81;
        wsm[i] = (co < COUT) ? w[(co * CIN + ci) * 81 + tap] : 0.f;
    }
    for (int i = tid; i < 2 * CIN * 26; i += 288) {
        int h = i / (CIN * 26), r = i % (CIN * 26);
        int ci = r / 26, rr = r % 26;
        float* rowp = pl + h * PLN + ci * CSTR + rr * RSTR;
        if (rr == 0 || rr == 25) {
            for (int c = 3; c <= 28; ++c) rowp[c] = 0.f;
        } else {
            rowp[3] = 0.f; rowp[28] = 0.f;
        }
    }

    u64 acc[COP][4];
#pragma unroll
    for (int cp = 0; cp < COP; ++cp)
#pragma unroll
        for (int o = 0; o < 4; ++o) acc[cp][o] = 0ull;

    for (int j1 = 0; j1 < 3; ++j1) {
        int y1 = x1 + j1 - 1;
        if ((unsigned)y1 >= 24u) continue;     // CTA-uniform skip (zero contribution)
        for (int j2 = 0; j2 < 3; ++j2) {
            __syncthreads();
            for (int t = tid; t < 2 * CIN * 24; t += 288) {
                int h = t / (CIN * 24), r = t % (CIN * 24);
                int ci = r / 24, rr = 1 + r % 24;
                int y2 = bx * 2 + h + j2 - 1;
                float* dst = pl + h * PLN + ci * CSTR + rr * RSTR + 4;
                if ((unsigned)y2 < 24u) {
                    const float* src = in + ((((size_t)b * CIN + ci) * 24 + y1) * 24 + y2) * POOL_P
                                          + (rr - 1) * 24;
#pragma unroll
                    for (int c = 0; c < 6; ++c)
                        *(float4*)(dst + c * 4) = *(const float4*)(src + c * 4);
                } else {
                    float4 z = make_float4(0.f, 0.f, 0.f, 0.f);
#pragma unroll
                    for (int c = 0; c < 6; ++c) *(float4*)(dst + c * 4) = z;
                }
            }
            __syncthreads();

            const float* base = pl + half * PLN;
            for (int ci = 0; ci < CIN; ++ci) {
#pragma unroll
                for (int j3 = 0; j3 < 3; ++j3) {
                    const float* r0 = base + ci * CSTR + (x3 + j3) * RSTR + 3 + x4;
                    const float* r1 = r0 + RSTR;
                    u64 vd0[4], vd1[4];
#pragma unroll
                    for (int t = 0; t < 4; ++t) {
                        float a = r0[t]; vd0[t] = pack2(a, a);
                        float c2 = r1[t]; vd1[t] = pack2(c2, c2);
                    }
                    const float* wb = wsm + (ci * 81 + j1 * 27 + j2 * 9 + j3 * 3) * CP2;
#pragma unroll
                    for (int j4 = 0; j4 < 3; ++j4) {
#pragma unroll
                        for (int cp = 0; cp < COP; ++cp) {
                            u64 wp = *reinterpret_cast<const u64*>(wb + j4 * CP2 + cp * 2);
                            fma2(acc[cp][0], wp, vd0[j4]);
                            fma2(acc[cp][1], wp, vd0[j4 + 1]);
                            fma2(acc[cp][2], wp, vd1[j4]);
                            fma2(acc[cp][3], wp, vd1[j4 + 1]);
                        }
                    }
                }
            }
        }
    }

    int pos0 = x3 * 24 + x4;
#pragma unroll
    for (int cp = 0; cp < COP; ++cp) {
        int co0 = 2 * cp, co1 = co0 + 1;
        float2 q0 = unpack2(acc[cp][0]);
        float2 q1 = unpack2(acc[cp][1]);
        float2 q2 = unpack2(acc[cp][2]);
        float2 q3 = unpack2(acc[cp][3]);
        float b0 = bias[co0];
        size_t base0 = ((((size_t)b * COUT + co0) * 24 + x1) * 24 + x2) * POOL_P + pos0;
        *(float2*)(out + base0)      = make_float2(fmaxf(q0.x + b0, 0.f), fmaxf(q1.x + b0, 0.f));
        *(float2*)(out + base0 + 24) = make_float2(fmaxf(q2.x + b0, 0.f), fmaxf(q3.x + b0, 0.f));
        if (co1 < COUT) {
            float b1 = bias[co1];
            size_t base1 = ((((size_t)b * COUT + co1) * 24 + x1) * 24 + x2) * POOL_P + pos0;
            *(float2*)(out + base1)      = make_float2(fmaxf(q0.y + b1, 0.f), fmaxf(q1.y + b1, 0.f));
            *(float2*)(out + base1 + 24) = make_float2(fmaxf(q2.y + b1, 0.f), fmaxf(q3.y + b1, 0.f));
        }
    }
}

// ---------------------------------------------------------------------------
// 6a) Conv1 (CIN=1): preload ALL 12 distinct haloed planes once.
//     Invalid-j1 tap groups skipped CTA-uniformly.
// ---------------------------------------------------------------------------
template <int COUT>
__global__ __launch_bounds__(288) void conv4d_cin1_kernel(
    const float* __restrict__ in, const float* __restrict__ w,
    const float* __restrict__ bias, float* __restrict__ out) {
    constexpr int CP2 = (COUT + 1) & ~1;
    constexpr int COP = CP2 / 2;
    constexpr int WPAD = (81 * CP2 + 3) & ~3;
    extern __shared__ float sm[];
    float* wsm = sm;                    // [81][CP2]
    float* pl = sm + WPAD;              // [12][CSTR]

    int tid = threadIdx.x;
    int b = blockIdx.z, x1 = blockIdx.y, bx = blockIdx.x;
    int half = tid / 144, u = tid % 144;
    int x3 = 2 * (u / 12), x4 = 2 * (u % 12);
    int x2 = bx * 2 + half;

    for (int i = tid; i < 81 * CP2; i += 288) {
        int co = i % CP2, tap = i / CP2;
        wsm[i] = (co < COUT) ? w[co * 81 + tap] : 0.f;
    }
    for (int i = tid; i < 12 * 26; i += 288) {
        int p = i / 26, rr = i % 26;
        float* rowp = pl + p * CSTR + rr * RSTR;
        if (rr == 0 || rr == 25) {
            for (int c = 3; c <= 28; ++c) rowp[c] = 0.f;
        } else {
            rowp[3] = 0.f; rowp[28] = 0.f;
        }
    }
    {
        int p = tid / 24, rr = 1 + tid % 24;
        int y1 = x1 + (p >> 2) - 1;
        int y2 = bx * 2 + (p & 3) - 1;
        float* dst = pl + p * CSTR + rr * RSTR + 4;
        if ((unsigned)y1 < 24u && (unsigned)y2 < 24u) {
            const float* src = in + (((size_t)b * 24 + y1) * 24 + y2) * POOL_P + (rr - 1) * 24;
#pragma unroll
            for (int c = 0; c < 6; ++c)
                *(float4*)(dst + c * 4) = *(const float4*)(src + c * 4);
        } else {
            float4 z = make_float4(0.f, 0.f, 0.f, 0.f);
#pragma unroll
            for (int c = 0; c < 6; ++c) *(float4*)(dst + c * 4) = z;
        }
    }
    __syncthreads();

    u64 acc[COP][4];
#pragma unroll
    for (int cp = 0; cp < COP; ++cp)
#pragma unroll
        for (int o = 0; o < 4; ++o) acc[cp][o] = 0ull;

#pragma unroll
    for (int g = 0; g < 9; ++g) {
        int j1 = g / 3, j2 = g % 3;
        if ((unsigned)(x1 + j1 - 1) >= 24u) continue;   // CTA-uniform skip
        const float* base = pl + (j1 * 4 + j2 + half) * CSTR;
#pragma unroll
        for (int j3 = 0; j3 < 3; ++j3) {
            const float* r0 = base + (x3 + j3) * RSTR + 3 + x4;
            const float* r1 = r0 + RSTR;
            u64 vd0[4], vd1[4];
#pragma unroll
            for (int t = 0; t < 4; ++t) {
                float a = r0[t]; vd0[t] = pack2(a, a);
                float c2 = r1[t]; vd1[t] = pack2(c2, c2);
            }
            const float* wb = wsm + (j1 * 27 + j2 * 9 + j3 * 3) * CP2;
#pragma unroll
            for (int j4 = 0; j4 < 3; ++j4) {
#pragma unroll
                for (int cp = 0; cp < COP; ++cp) {
                    u64 wp = *reinterpret_cast<const u64*>(wb + j4 * CP2 + cp * 2);
                    fma2(acc[cp][0], wp, vd0[j4]);
                    fma2(acc[cp][1], wp, vd0[j4 + 1]);
                    fma2(acc[cp][2], wp, vd1[j4]);
                    fma2(acc[cp][3], wp, vd1[j4 + 1]);
                }
            }
        }
    }

    int pos0 = x3 * 24 + x4;
#pragma unroll
    for (int cp = 0; cp < COP; ++cp) {
        int co0 = 2 * cp, co1 = co0 + 1;
        float2 q0 = unpack2(acc[cp][0]);
        float2 q1 = unpack2(acc[cp][1]);
        float2 q2 = unpack2(acc[cp][2]);
        float2 q3 = unpack2(acc[cp][3]);
        float b0 = bias[co0];
        size_t base0 = ((((size_t)b * COUT + co0) * 24 + x1) * 24 + x2) * POOL_P + pos0;
        *(float2*)(out + base0)      = make_float2(fmaxf(q0.x + b0, 0.f), fmaxf(q1.x + b0, 0.f));
        *(float2*)(out + base0 + 24) = make_float2(fmaxf(q2.x + b0, 0.f), fmaxf(q3.x + b0, 0.f));
        if (co1 < COUT) {
            float b1 = bias[co1];
            size_t base1 = ((((size_t)b * COUT + co1) * 24 + x1) * 24 + x2) * POOL_P + pos0;
            *(float2*)(out + base1)      = make_float2(fmaxf(q0.y + b1, 0.f), fmaxf(q1.y + b1, 0.f));
            *(float2*)(out + base1 + 24) = make_float2(fmaxf(q2.y + b1, 0.f), fmaxf(q3.y + b1, 0.f));
        }
    }
}

// ---------------------------------------------------------------------------
// 6b) Conv3 (COUT=1): row-pair f32x2; invalid-j1 taps skipped CTA-uniformly.
// ---------------------------------------------------------------------------
template <int CIN>
__global__ __launch_bounds__(288) void conv4d_c1_kernel(
    const float* __restrict__ in, const float* __restrict__ w,
    const float* __restrict__ bias, float* __restrict__ out) {
    constexpr int WPAD = (2 * CIN * 81 + 3) & ~3;
    constexpr int PLN = CIN * CSTR;
    extern __shared__ float sm[];
    float* wsm = sm;
    float* pl = sm + WPAD;

    int tid = threadIdx.x;
    int b = blockIdx.z, x1 = blockIdx.y, bx = blockIdx.x;
    int half = tid / 144, u = tid % 144;
    int x3 = 2 * (u / 12), x4 = 2 * (u % 12);
    int x2 = bx * 2 + half;

    for (int i = tid; i < CIN * 81; i += 288) {
        float v = w[i];
        wsm[2 * i] = v; wsm[2 * i + 1] = v;
    }
    for (int i = tid; i < 2 * CIN * 26; i += 288) {
        int h = i / (CIN * 26), r = i % (CIN * 26);
        int ci = r / 26, rr = r % 26;
        float* rowp = pl + h * PLN + ci * CSTR + rr * RSTR;
        if (rr == 0 || rr == 25) {
            for (int c = 3; c <= 28; ++c) rowp[c] = 0.f;
        } else {
            rowp[3] = 0.f; rowp[28] = 0.f;
        }
    }

    u64 acc[2] = {0ull, 0ull};

    for (int j1 = 0; j1 < 3; ++j1) {
        int y1 = x1 + j1 - 1;
        if ((unsigned)y1 >= 24u) continue;     // CTA-uniform skip
        for (int j2 = 0; j2 < 3; ++j2) {
            __syncthreads();
            for (int t = tid; t < 2 * CIN * 24; t += 288) {
                int h = t / (CIN * 24), r = t % (CIN * 24);
                int ci = r / 24, rr = 1 + r % 24;
                int y2 = bx * 2 + h + j2 - 1;
                float* dst = pl + h * PLN + ci * CSTR + rr * RSTR + 4;
                if ((unsigned)y2 < 24u) {
                    const float* src = in + ((((size_t)b * CIN + ci) * 24 + y1) * 24 + y2) * POOL_P
                                          + (rr - 1) * 24;
#pragma unroll
                    for (int c = 0; c < 6; ++c)
                        *(float4*)(dst + c * 4) = *(const float4*)(src + c * 4);
                } else {
                    float4 z = make_float4(0.f, 0.f, 0.f, 0.f);
#pragma unroll
                    for (int c = 0; c < 6; ++c) *(float4*)(dst + c * 4) = z;
                }
            }
            __syncthreads();

            const float* base = pl + half * PLN;
            for (int ci = 0; ci < CIN; ++ci) {
#pragma unroll
                for (int j3 = 0; j3 < 3; ++j3) {
                    const float* r0 = base + ci * CSTR + (x3 + j3) * RSTR + 3 + x4;
                    const float* r1 = r0 + RSTR;
                    u64 vd[4];
#pragma unroll
                    for (int t = 0; t < 4; ++t) vd[t] = pack2(r0[t], r1[t]);
                    const u64* wb = reinterpret_cast<const u64*>(
                        wsm + 2 * (ci * 81 + j1 * 27 + j2 * 9 + j3 * 3));
#pragma unroll
                    for (int j4 = 0; j4 < 3; ++j4) {
                        u64 wp = wb[j4];
                        fma2(acc[0], wp, vd[j4]);
                        fma2(acc[1], wp, vd[j4 + 1]);
                    }
                }
            }
        }
    }

    float b0 = bias[0];
    float2 c0 = unpack2(acc[0]);
    float2 c1 = unpack2(acc[1]);
    size_t base0 = (((size_t)b * 24 + x1) * 24 + x2) * POOL_P + x3 * 24 + x4;
    *(float2*)(out + base0)      = make_float2(fmaxf(c0.x + b0, 0.f), fmaxf(c1.x + b0, 0.f));
    *(float2*)(out + base0 + 24) = make_float2(fmaxf(c0.y + b0, 0.f), fmaxf(c1.y + b0, 0.f));
}

// host-side smem mirrors
static inline size_t conv_smem_bytes(int cin, int cout) {
    int cp2 = (cout + 1) & ~1;
    size_t wpad = ((size_t)cin * 81 * cp2 + 3) & ~(size_t)3;
    return (wpad + 2 * (size_t)cin * CSTR) * 4;
}
static inline size_t conv_cin1_smem_bytes(int cout) {
    int cp2 = (cout + 1) & ~1;
    size_t wpad = ((size_t)81 * cp2 + 3) & ~(size_t)3;
    return (wpad + 12 * (size_t)CSTR) * 4;
}
static inline size_t conv_c1_smem_bytes(int cin) {
    size_t wpad = (2 * (size_t)cin * 81 + 3) & ~(size_t)3;
    return (wpad + 2 * (size_t)cin * CSTR) * 4;
}

// ---------------------------------------------------------------------------
// Launch
// ---------------------------------------------------------------------------
extern "C" void kernel_launch(void* const* d_in, const int* in_sizes, int n_in,
                              void* d_out, int out_size) {
    const float* fA = (const float*)d_in[0];
    const float* fB = (const float*)d_in[1];
    const float* w1 = (const float*)d_in[2];
    const float* b1 = (const float*)d_in[3];
    const float* w2 = (const float*)d_in[4];
    const float* b2 = (const float*)d_in[5];
    const float* w3 = (const float*)d_in[6];
    const float* b3 = (const float*)d_in[7];
    float* out = (float*)d_out;

    float *gA, *gB, *invA, *invB, *cpool, *x1b, *x2b, *amax, *bmax;
    cudaGetSymbolAddress((void**)&gA, g_A);
    cudaGetSymbolAddress((void**)&gB, g_B);
    cudaGetSymbolAddress((void**)&invA, g_invnA);
    cudaGetSymbolAddress((void**)&invB, g_invnB);
    cudaGetSymbolAddress((void**)&cpool, g_cpool);
    cudaGetSymbolAddress((void**)&x1b, g_x1);
    cudaGetSymbolAddress((void**)&x2b, g_x2);
    cudaGetSymbolAddress((void**)&amax, g_amax);
    cudaGetSymbolAddress((void**)&bmax, g_bmax);

    size_t sm1 = conv_cin1_smem_bytes(10);   // ~48.2 KB
    size_t sm2 = conv_smem_bytes(10, 10);    // ~107.3 KB (2 CTAs/SM)
    size_t sm3 = conv_c1_smem_bytes(10);     // ~81.4 KB (2 CTAs/SM)
    size_t smg = 3 * 2 * STAGE_FLOATS * 4;   // 96 KB

    cudaFuncSetAttribute(gemm_pool_kernel, cudaFuncAttributeMaxDynamicSharedMemorySize, (int)smg);
    cudaFuncSetAttribute(conv4d_cin1_kernel<10>, cudaFuncAttributeMaxDynamicSharedMemorySize, (int)sm1);
    cudaFuncSetAttribute(conv4d_v4_kernel<10, 10>, cudaFuncAttributeMaxDynamicSharedMemorySize, (int)sm2);
    cudaFuncSetAttribute(conv4d_c1_kernel<10>, cudaFuncAttributeMaxDynamicSharedMemorySize, (int)sm3);

    // 1) inverse norms
    invnorm_kernel<<<(2 * BATCH * HW) / 256, 256>>>(fA, fB);

    // 2) transpose + normalize + tf32 round (A and B in ONE launch)
    transnorm_kernel<<<dim3(72, 32, 16), 256>>>(fA, fB, invA, invB, gA, gB);

    // 3) TF32 GEMM + pool + relu/L2
    gemm_pool_kernel<<<dim3(18, 18, BATCH), 128, smg>>>(gA, gB, cpool);

    // 4) mutual matching #1 (in place)
    rowcolmax_kernel<<<dim3(POOL_P + POOL_P / 64, BATCH), 64>>>(cpool, amax, bmax);
    mm_kernel<<<(POS_TOTAL + 255) / 256, 256>>>(cpool, amax, bmax, cpool);

    // 5) neighbourhood consensus convs
    dim3 cgrid(12, 24, BATCH);
    conv4d_cin1_kernel<10><<<cgrid, 288, sm1>>>(cpool, w1, b1, x1b);
    conv4d_v4_kernel<10, 10><<<cgrid, 288, sm2>>>(x1b, w2, b2, x2b);
    conv4d_c1_kernel<10><<<cgrid, 288, sm3>>>(x2b, w3, b3, cpool);

    // 6) mutual matching #2 -> output
    rowcolmax_kernel<<<dim3(POOL_P + POOL_P / 64, BATCH), 64>>>(cpool, amax, bmax);
    mm_kernel<<<(POS_TOTAL + 255) / 256, 256>>>(cpool, amax, bmax, out);

    (void)in_sizes; (void)n_in; (void)out_size;
}

// round 13
// speedup vs baseline: 1.7934x; 1.0173x over previous
#include <cuda_runtime.h>
#include <cuda_bf16.h>

// ---------------------------------------------------------------------------
// Problem constants
// ---------------------------------------------------------------------------
#define BATCH 8
#define CHANNELS 1024
#define HW 2304           // 48*48
#define POOL_P 576        // 24*24
#define POS_TOTAL (BATCH*POOL_P*POOL_P)   // 2,654,208
#define EPS_L2 1e-6f
#define EPS_MM 1e-5f

typedef unsigned long long u64;

// ---------------------------------------------------------------------------
// Scratch (device globals; no allocation allowed)
// ---------------------------------------------------------------------------
__device__ float g_A[BATCH * HW * CHANNELS];
__device__ float g_B[BATCH * HW * CHANNELS];
__device__ float g_invnA[BATCH * HW];
__device__ float g_invnB[BATCH * HW];
__device__ float g_cpool[POS_TOTAL];
__device__ float g_x1[BATCH * 10 * POOL_P * POOL_P];
__device__ float g_x2[BATCH * 10 * POOL_P * POOL_P];
__device__ float g_amax[BATCH * POOL_P];      // max -> reciprocal (in place)
__device__ float g_bmax[BATCH * POOL_P];

// ---------------------------------------------------------------------------
// Helpers
// ---------------------------------------------------------------------------
__device__ __forceinline__ unsigned smem_u32(const void* p) {
    return (unsigned)__cvta_generic_to_shared(p);
}
__device__ __forceinline__ u64 pack2(float a, float b) {
    u64 r; asm("mov.b64 %0, {%1, %2};" : "=l"(r) : "f"(a), "f"(b)); return r;
}
__device__ __forceinline__ void fma2(u64& d, u64 a, u64 b) {
    asm("fma.rn.f32x2 %0, %1, %2, %0;" : "+l"(d) : "l"(a), "l"(b));
}
__device__ __forceinline__ float2 unpack2(u64 v) {
    float2 r; asm("mov.b64 {%0, %1}, %2;" : "=f"(r.x), "=f"(r.y) : "l"(v)); return r;
}
__device__ __forceinline__ float tf32r(float v) {
    unsigned t; asm("cvt.rna.tf32.f32 %0, %1;" : "=r"(t) : "f"(v));
    return __uint_as_float(t);
}

// ---------------------------------------------------------------------------
// 1) inverse L2 norm per (b, hw)
// ---------------------------------------------------------------------------
__global__ void invnorm_kernel(const float* __restrict__ A, const float* __restrict__ B) {
    int t = blockIdx.x * blockDim.x + threadIdx.x;
    if (t >= 2 * BATCH * HW) return;
    const float* f = (t < BATCH * HW) ? A : B;
    float* o = (t < BATCH * HW) ? g_invnA : g_invnB;
    int idx = t % (BATCH * HW);
    int b = idx / HW, hw = idx % HW;
    const float* p = f + (size_t)b * CHANNELS * HW + hw;
    float s = 0.f;
#pragma unroll 16
    for (int c = 0; c < CHANNELS; ++c) {
        float v = p[(size_t)c * HW];
        s = fmaf(v, v, s);
    }
    o[idx] = rsqrtf(s + EPS_L2);
}

// ---------------------------------------------------------------------------
// 2) transpose + normalize + tf32-round into MMA-fragment layout (one launch)
// ---------------------------------------------------------------------------
__global__ __launch_bounds__(256) void transnorm_kernel(
    const float* __restrict__ fA, const float* __restrict__ fB,
    const float* __restrict__ invA, const float* __restrict__ invB,
    float* __restrict__ outA, float* __restrict__ outB) {
    __shared__ float sm[32][33];
    int zz = blockIdx.z;
    int mode = zz >> 3;
    int b = zz & 7;
    const float* f = mode ? fB : fA;
    const float* invn = mode ? invB : invA;
    float* out = mode ? outB : outA;

    int pb = blockIdx.x;
    int c0 = blockIdx.y * 32;
    int g0 = pb * 8;
    int hbase = (g0 / 24) * 2;
    int wbase = (g0 % 24) * 2;
    int tid = threadIdx.x;

    for (int idx = tid; idx < 1024; idx += 256) {
        int ci = idx >> 5, pos = idx & 31;
        int hh = pos >> 4, ww = pos & 15;
        int hw = (hbase + hh) * 48 + wbase + ww;
        float v = f[((size_t)b * CHANNELS + c0 + ci) * HW + hw] * invn[b * HW + hw];
        int p_in = ((ww >> 1) << 2) | (hh << 1) | (ww & 1);
        sm[p_in][ci] = tf32r(v);
    }
    __syncthreads();

    int p0 = pb * 32;
    if (mode == 0) {
        int mt = tid >> 7, kt = (tid >> 5) & 3, lane = tid & 31;
        int rowin = lane >> 2, colin = lane & 3;
        float4 v;
        v.x = sm[mt * 16 + rowin][kt * 8 + colin];
        v.y = sm[mt * 16 + rowin + 8][kt * 8 + colin];
        v.z = sm[mt * 16 + rowin][kt * 8 + colin + 4];
        v.w = sm[mt * 16 + rowin + 8][kt * 8 + colin + 4];
        int rowblk = p0 >> 7;
        int mtile_g = ((p0 >> 4) & 7) + mt;
        int ktile_g = (c0 >> 3) + kt;
        size_t off = ((((size_t)b * 18 + rowblk) * 128 + ktile_g) * 8 + mtile_g) * 128
                     + lane * 4;
        *(float4*)(out + off) = v;
    } else {
        int colblk = p0 >> 7;
#pragma unroll
        for (int i = 0; i < 2; ++i) {
            int id = tid + i * 256;
            int nt = id >> 7, kt = (id >> 5) & 3, lane = id & 31;
            int rowin = lane >> 2, colin = lane & 3;
            float2 v;
            v.x = sm[nt * 8 + rowin][kt * 8 + colin];
            v.y = sm[nt * 8 + rowin][kt * 8 + colin + 4];
            int ntile_g = ((p0 >> 3) & 15) + nt;
            int ktile_g = (c0 >> 3) + kt;
            size_t off = ((((size_t)b * 18 + colblk) * 128 + ktile_g) * 16 + ntile_g) * 64
                         + lane * 2;
            *(float2*)(out + off) = v;
        }
    }
}

// ---------------------------------------------------------------------------
// 3) batched TF32 GEMM + fused 4x4 max-pool + relu/L2  (R8 config, frozen)
// ---------------------------------------------------------------------------
#define STAGE_FLOATS 4096   // 4 ktiles * 1024 floats

__global__ __launch_bounds__(128) void gemm_pool_kernel(
    const float* __restrict__ A, const float* __restrict__ B,
    float* __restrict__ out) {
    extern __shared__ char smem_raw[];
    float* As = (float*)smem_raw;            // [3][4096]
    float* Bs = As + 3 * STAGE_FLOATS;       // [3][4096]
    float* Cs = (float*)smem_raw;            // reused: [128][132]

    int b = blockIdx.z;
    const float* Ag = A + (size_t)b * HW * CHANNELS + (size_t)blockIdx.y * 128 * 1024;
    const float* Bg = B + (size_t)b * HW * CHANNELS + (size_t)blockIdx.x * 128 * 1024;

    int tid = threadIdx.x, lane = tid & 31, wid = tid >> 5;
    int wm = wid >> 1, wn = wid & 1;   // 2x2 warp grid, warp tile 64x64

    float acc[4][8][4];
#pragma unroll
    for (int i = 0; i < 4; ++i)
#pragma unroll
        for (int j = 0; j < 8; ++j)
#pragma unroll
            for (int k = 0; k < 4; ++k) acc[i][j][k] = 0.f;

    auto load_stage = [&](int s, int kt) {
        const float* ga = Ag + (size_t)kt * STAGE_FLOATS;
        const float* gb = Bg + (size_t)kt * STAGE_FLOATS;
#pragma unroll
        for (int i = 0; i < 8; ++i) {
            int idx = tid + i * 128;
            unsigned sa = smem_u32(As + s * STAGE_FLOATS + idx * 4);
            asm volatile("cp.async.cg.shared.global [%0], [%1], 16;\n" :: "r"(sa), "l"(ga + idx * 4));
            unsigned sb = smem_u32(Bs + s * STAGE_FLOATS + idx * 4);
            asm volatile("cp.async.cg.shared.global [%0], [%1], 16;\n" :: "r"(sb), "l"(gb + idx * 4));
        }
        asm volatile("cp.async.commit_group;\n");
    };

    const int KT = CHANNELS / 32;
    load_stage(0, 0);
    load_stage(1, 1);
    for (int kt = 0; kt < KT; ++kt) {
        if (kt + 2 < KT) {
            asm volatile("cp.async.wait_group 1;\n");
        } else {
            asm volatile("cp.async.wait_group 0;\n");
        }
        __syncthreads();
        if (kt + 2 < KT) load_stage((kt + 2) % 3, kt + 2);
        int cur = kt % 3;
        const float* Ab = As + cur * STAGE_FLOATS;
        const float* Bb = Bs + cur * STAGE_FLOATS;
#pragma unroll
        for (int kk = 0; kk < 4; ++kk) {
            uint2 bf[8];
#pragma unroll
            for (int ni = 0; ni < 8; ++ni)
                bf[ni] = *(const uint2*)(Bb + ((kk * 16 + wn * 8 + ni) * 32 + lane) * 2);
#pragma unroll
            for (int mi = 0; mi < 4; ++mi) {
                uint4 af = *(const uint4*)(Ab + ((kk * 8 + wm * 4 + mi) * 32 + lane) * 4);
#pragma unroll
                for (int ni = 0; ni < 8; ++ni) {
                    asm volatile(
                        "mma.sync.aligned.m16n8k8.row.col.f32.tf32.tf32.f32 "
                        "{%0,%1,%2,%3}, {%4,%5,%6,%7}, {%8,%9}, {%0,%1,%2,%3};\n"
                        : "+f"(acc[mi][ni][0]), "+f"(acc[mi][ni][1]),
                          "+f"(acc[mi][ni][2]), "+f"(acc[mi][ni][3])
                        : "r"(af.x), "r"(af.y), "r"(af.z), "r"(af.w),
                          "r"(bf[ni].x), "r"(bf[ni].y));
                }
            }
        }
    }
    __syncthreads();

#pragma unroll
    for (int mi = 0; mi < 4; ++mi) {
#pragma unroll
        for (int ni = 0; ni < 8; ++ni) {
            int r0 = wm * 64 + mi * 16 + (lane >> 2);
            int c0 = wn * 64 + ni * 8 + (lane & 3) * 2;
            Cs[r0 * 132 + c0]           = acc[mi][ni][0];
            Cs[r0 * 132 + c0 + 1]       = acc[mi][ni][1];
            Cs[(r0 + 8) * 132 + c0]     = acc[mi][ni][2];
            Cs[(r0 + 8) * 132 + c0 + 1] = acc[mi][ni][3];
        }
    }
    __syncthreads();

#pragma unroll
    for (int o = 0; o < 8; ++o) {
        int idx = tid * 8 + o;
        int pp = idx >> 5, qq = idx & 31;
        float m = -1e30f;
#pragma unroll
        for (int i = 0; i < 4; ++i)
#pragma unroll
            for (int j = 0; j < 4; ++j)
                m = fmaxf(m, Cs[(pp * 4 + i) * 132 + qq * 4 + j]);
        m = fmaxf(m, 0.f);
        float v = m * rsqrtf(m * m + EPS_L2);
        out[((size_t)b * POOL_P + blockIdx.y * 32 + pp) * POOL_P + blockIdx.x * 32 + qq] = v;
    }
}

// ---------------------------------------------------------------------------
// 4) fused single-pass row+col maxes (values >= 0).
//    grid (9, BATCH), 256 thr. Block owns a 64-row band: warp w handles rows
//    w*8..w*8+7 (full row max -> direct store); lanes keep 18 column partials
//    in registers -> smem col tile (shared atomicMax) -> global atomicMax.
//    bmax must be zeroed beforehand (cudaMemsetAsync).
// ---------------------------------------------------------------------------
__global__ __launch_bounds__(256) void maxfused_kernel(
    const float* __restrict__ X, float* __restrict__ amax, float* __restrict__ bmax) {
    __shared__ int colm_s[POOL_P];
    int b = blockIdx.y;
    int r0 = blockIdx.x * 64;
    int tid = threadIdx.x, lane = tid & 31, wid = tid >> 5;

    for (int i = tid; i < POOL_P; i += 256) colm_s[i] = 0;
    __syncthreads();

    float colm[18];
#pragma unroll
    for (int i = 0; i < 18; ++i) colm[i] = 0.f;

    const float* base = X + (size_t)b * POOL_P * POOL_P;
#pragma unroll
    for (int rr = 0; rr < 8; ++rr) {
        int row = r0 + wid * 8 + rr;
        const float* p = base + (size_t)row * POOL_P;
        float rm = 0.f;
#pragma unroll
        for (int i = 0; i < 18; ++i) {
            float v = p[lane + i * 32];
            rm = fmaxf(rm, v);
            colm[i] = fmaxf(colm[i], v);
        }
#pragma unroll
        for (int s = 16; s; s >>= 1) rm = fmaxf(rm, __shfl_down_sync(0xffffffffu, rm, s));
        if (lane == 0) amax[b * POOL_P + row] = rm;
    }
#pragma unroll
    for (int i = 0; i < 18; ++i)
        atomicMax(&colm_s[lane + i * 32], __float_as_int(colm[i]));
    __syncthreads();
    for (int i = tid; i < POOL_P; i += 256)
        atomicMax((int*)&bmax[b * POOL_P + i], colm_s[i]);
}

// convert max -> 1/(max+eps) for both tables (4608 each)
__global__ void recip_kernel(float* __restrict__ amax, float* __restrict__ bmax) {
    int i = blockIdx.x * blockDim.x + threadIdx.x;
    if (i < BATCH * POOL_P) {
        amax[i] = 1.0f / (amax[i] + EPS_MM);
        bmax[i] = 1.0f / (bmax[i] + EPS_MM);
    }
}

// ---------------------------------------------------------------------------
// 5) mutual matching, float4: out = c * (c*ainv[p]) * (c*binv[q])
// ---------------------------------------------------------------------------
__global__ __launch_bounds__(256) void mm_kernel(
    const float* __restrict__ X, const float* __restrict__ am,
    const float* __restrict__ bm, float* __restrict__ O) {
    int i4 = blockIdx.x * blockDim.x + threadIdx.x;   // float4 index
    if (i4 >= POS_TOTAL / 4) return;
    int i = i4 * 4;
    int q = i % POOL_P;                                // multiple of 4
    int pr = (i / POOL_P) % POOL_P;
    int b = i / (POOL_P * POOL_P);
    float a = am[b * POOL_P + pr];
    const float* bp = bm + b * POOL_P + q;
    float4 c = *(const float4*)(X + i);
    float4 o;
    o.x = c.x * (c.x * a) * (c.x * bp[0]);
    o.y = c.y * (c.y * a) * (c.y * bp[1]);
    o.z = c.z * (c.z * a) * (c.z * bp[2]);
    o.w = c.w * (c.w * a) * (c.w * bp[3]);
    *(float4*)(O + i) = o;
}

// ---------------------------------------------------------------------------
// 6) Conv4d FFMA2 v4 (conv2): 2x2 tile/thread, CTA-uniform j1 skip.
// ---------------------------------------------------------------------------
#define RSTR 36              // plane row stride (floats)
#define CSTR (26 * RSTR)     // 936 floats per channel

template <int CIN, int COUT>
__global__ __launch_bounds__(288) void conv4d_v4_kernel(
    const float* __restrict__ in, const float* __restrict__ w,
    const float* __restrict__ bias, float* __restrict__ out) {
    constexpr int CP2 = (COUT + 1) & ~1;
    constexpr int COP = CP2 / 2;
    constexpr int WPAD = (CIN * 81 * CP2 + 3) & ~3;
    constexpr int PLN = CIN * CSTR;
    extern __shared__ float sm[];
    float* wsm = sm;
    float* pl = sm + WPAD;

    int tid = threadIdx.x;
    int b = blockIdx.z, x1 = blockIdx.y, bx = blockIdx.x;
    int half = tid / 144, u = tid % 144;
    int x3 = 2 * (u / 12), x4 = 2 * (u % 12);
    int x2 = bx * 2 + half;

    for (int i = tid; i < CIN * 81 * CP2; i += 288) {
        int co = i % CP2;
        int rest = i / CP2;
        int ci = rest / 81, tap = rest % 81;
        wsm[i] = (co < COUT) ? w[(co * CIN + ci) * 81 + tap] : 0.f;
    }
    for (int i = tid; i < 2 * CIN * 26; i += 288) {
        int h = i / (CIN * 26), r = i % (CIN * 26);
        int ci = r / 26, rr = r % 26;
        float* rowp = pl + h * PLN + ci * CSTR + rr * RSTR;
        if (rr == 0 || rr == 25) {
            for (int c = 3; c <= 28; ++c) rowp[c] = 0.f;
        } else {
            rowp[3] = 0.f; rowp[28] = 0.f;
        }
    }

    u64 acc[COP][4];
#pragma unroll
    for (int cp = 0; cp < COP; ++cp)
#pragma unroll
        for (int o = 0; o < 4; ++o) acc[cp][o] = 0ull;

    for (int j1 = 0; j1 < 3; ++j1) {
        int y1 = x1 + j1 - 1;
        if ((unsigned)y1 >= 24u) continue;
        for (int j2 = 0; j2 < 3; ++j2) {
            __syncthreads();
            for (int t = tid; t < 2 * CIN * 24; t += 288) {
                int h = t / (CIN * 24), r = t % (CIN * 24);
                int ci = r / 24, rr = 1 + r % 24;
                int y2 = bx * 2 + h + j2 - 1;
                float* dst = pl + h * PLN + ci * CSTR + rr * RSTR + 4;
                if ((unsigned)y2 < 24u) {
                    const float* src = in + ((((size_t)b * CIN + ci) * 24 + y1) * 24 + y2) * POOL_P
                                          + (rr - 1) * 24;
#pragma unroll
                    for (int c = 0; c < 6; ++c)
                        *(float4*)(dst + c * 4) = *(const float4*)(src + c * 4);
                } else {
                    float4 z = make_float4(0.f, 0.f, 0.f, 0.f);
#pragma unroll
                    for (int c = 0; c < 6; ++c) *(float4*)(dst + c * 4) = z;
                }
            }
            __syncthreads();

            const float* base = pl + half * PLN;
            for (int ci = 0; ci < CIN; ++ci) {
#pragma unroll
                for (int j3 = 0; j3 < 3; ++j3) {
                    const float* r0 = base + ci * CSTR + (x3 + j3) * RSTR + 3 + x4;
                    const float* r1 = r0 + RSTR;
                    u64 vd0[4], vd1[4];
#pragma unroll
                    for (int t = 0; t < 4; ++t) {
                        float a = r0[t]; vd0[t] = pack2(a, a);
                        float c2 = r1[t]; vd1[t] = pack2(c2, c2);
                    }
                    const float* wb = wsm + (ci * 81 + j1 * 27 + j2 * 9 + j3 * 3) * CP2;
#pragma unroll
                    for (int j4 = 0; j4 < 3; ++j4) {
#pragma unroll
                        for (int cp = 0; cp < COP; ++cp) {
                            u64 wp = *reinterpret_cast<const u64*>(wb + j4 * CP2 + cp * 2);
                            fma2(acc[cp][0], wp, vd0[j4]);
                            fma2(acc[cp][1], wp, vd0[j4 + 1]);
                            fma2(acc[cp][2], wp, vd1[j4]);
                            fma2(acc[cp][3], wp, vd1[j4 + 1]);
                        }
                    }
                }
            }
        }
    }

    int pos0 = x3 * 24 + x4;
#pragma unroll
    for (int cp = 0; cp < COP; ++cp) {
        int co0 = 2 * cp, co1 = co0 + 1;
        float2 q0 = unpack2(acc[cp][0]);
        float2 q1 = unpack2(acc[cp][1]);
        float2 q2 = unpack2(acc[cp][2]);
        float2 q3 = unpack2(acc[cp][3]);
        float b0 = bias[co0];
        size_t base0 = ((((size_t)b * COUT + co0) * 24 + x1) * 24 + x2) * POOL_P + pos0;
        *(float2*)(out + base0)      = make_float2(fmaxf(q0.x + b0, 0.f), fmaxf(q1.x + b0, 0.f));
        *(float2*)(out + base0 + 24) = make_float2(fmaxf(q2.x + b0, 0.f), fmaxf(q3.x + b0, 0.f));
        if (co1 < COUT) {
            float b1 = bias[co1];
            size_t base1 = ((((size_t)b * COUT + co1) * 24 + x1) * 24 + x2) * POOL_P + pos0;
            *(float2*)(out + base1)      = make_float2(fmaxf(q0.y + b1, 0.f), fmaxf(q1.y + b1, 0.f));
            *(float2*)(out + base1 + 24) = make_float2(fmaxf(q2.y + b1, 0.f), fmaxf(q3.y + b1, 0.f));
        }
    }
}

// ---------------------------------------------------------------------------
// 6a) Conv1 (CIN=1): preload ALL 12 distinct haloed planes once.
// ---------------------------------------------------------------------------
template <int COUT>
__global__ __launch_bounds__(288) void conv4d_cin1_kernel(
    const float* __restrict__ in, const float* __restrict__ w,
    const float* __restrict__ bias, float* __restrict__ out) {
    constexpr int CP2 = (COUT + 1) & ~1;
    constexpr int COP = CP2 / 2;
    constexpr int WPAD = (81 * CP2 + 3) & ~3;
    extern __shared__ float sm[];
    float* wsm = sm;                    // [81][CP2]
    float* pl = sm + WPAD;              // [12][CSTR]

    int tid = threadIdx.x;
    int b = blockIdx.z, x1 = blockIdx.y, bx = blockIdx.x;
    int half = tid / 144, u = tid % 144;
    int x3 = 2 * (u / 12), x4 = 2 * (u % 12);
    int x2 = bx * 2 + half;

    for (int i = tid; i < 81 * CP2; i += 288) {
        int co = i % CP2, tap = i / CP2;
        wsm[i] = (co < COUT) ? w[co * 81 + tap] : 0.f;
    }
    for (int i = tid; i < 12 * 26; i += 288) {
        int p = i / 26, rr = i % 26;
        float* rowp = pl + p * CSTR + rr * RSTR;
        if (rr == 0 || rr == 25) {
            for (int c = 3; c <= 28; ++c) rowp[c] = 0.f;
        } else {
            rowp[3] = 0.f; rowp[28] = 0.f;
        }
    }
    {
        int p = tid / 24, rr = 1 + tid % 24;
        int y1 = x1 + (p >> 2) - 1;
        int y2 = bx * 2 + (p & 3) - 1;
        float* dst = pl + p * CSTR + rr * RSTR + 4;
        if ((unsigned)y1 < 24u && (unsigned)y2 < 24u) {
            const float* src = in + (((size_t)b * 24 + y1) * 24 + y2) * POOL_P + (rr - 1) * 24;
#pragma unroll
            for (int c = 0; c < 6; ++c)
                *(float4*)(dst + c * 4) = *(const float4*)(src + c * 4);
        } else {
            float4 z = make_float4(0.f, 0.f, 0.f, 0.f);
#pragma unroll
            for (int c = 0; c < 6; ++c) *(float4*)(dst + c * 4) = z;
        }
    }
    __syncthreads();

    u64 acc[COP][4];
#pragma unroll
    for (int cp = 0; cp < COP; ++cp)
#pragma unroll
        for (int o = 0; o < 4; ++o) acc[cp][o] = 0ull;

#pragma unroll
    for (int g = 0; g < 9; ++g) {
        int j1 = g / 3, j2 = g % 3;
        if ((unsigned)(x1 + j1 - 1) >= 24u) continue;
        const float* base = pl + (j1 * 4 + j2 + half) * CSTR;
#pragma unroll
        for (int j3 = 0; j3 < 3; ++j3) {
            const float* r0 = base + (x3 + j3) * RSTR + 3 + x4;
            const float* r1 = r0 + RSTR;
            u64 vd0[4], vd1[4];
#pragma unroll
            for (int t = 0; t < 4; ++t) {
                float a = r0[t]; vd0[t] = pack2(a, a);
                float c2 = r1[t]; vd1[t] = pack2(c2, c2);
            }
            const float* wb = wsm + (j1 * 27 + j2 * 9 + j3 * 3) * CP2;
#pragma unroll
            for (int j4 = 0; j4 < 3; ++j4) {
#pragma unroll
                for (int cp = 0; cp < COP; ++cp) {
                    u64 wp = *reinterpret_cast<const u64*>(wb + j4 * CP2 + cp * 2);
                    fma2(acc[cp][0], wp, vd0[j4]);
                    fma2(acc[cp][1], wp, vd0[j4 + 1]);
                    fma2(acc[cp][2], wp, vd1[j4]);
                    fma2(acc[cp][3], wp, vd1[j4 + 1]);
                }
            }
        }
    }

    int pos0 = x3 * 24 + x4;
#pragma unroll
    for (int cp = 0; cp < COP; ++cp) {
        int co0 = 2 * cp, co1 = co0 + 1;
        float2 q0 = unpack2(acc[cp][0]);
        float2 q1 = unpack2(acc[cp][1]);
        float2 q2 = unpack2(acc[cp][2]);
        float2 q3 = unpack2(acc[cp][3]);
        float b0 = bias[co0];
        size_t base0 = ((((size_t)b * COUT + co0) * 24 + x1) * 24 + x2) * POOL_P + pos0;
        *(float2*)(out + base0)      = make_float2(fmaxf(q0.x + b0, 0.f), fmaxf(q1.x + b0, 0.f));
        *(float2*)(out + base0 + 24) = make_float2(fmaxf(q2.x + b0, 0.f), fmaxf(q3.x + b0, 0.f));
        if (co1 < COUT) {
            float b1 = bias[co1];
            size_t base1 = ((((size_t)b * COUT + co1) * 24 + x1) * 24 + x2) * POOL_P + pos0;
            *(float2*)(out + base1)      = make_float2(fmaxf(q0.y + b1, 0.f), fmaxf(q1.y + b1, 0.f));
            *(float2*)(out + base1 + 24) = make_float2(fmaxf(q2.y + b1, 0.f), fmaxf(q3.y + b1, 0.f));
        }
    }
}

// ---------------------------------------------------------------------------
// 6b) Conv3 (COUT=1): row-pair f32x2; CTA-uniform j1 skip.
// ---------------------------------------------------------------------------
template <int CIN>
__global__ __launch_bounds__(288) void conv4d_c1_kernel(
    const float* __restrict__ in, const float* __restrict__ w,
    const float* __restrict__ bias, float* __restrict__ out) {
    constexpr int WPAD = (2 * CIN * 81 + 3) & ~3;
    constexpr int PLN = CIN * CSTR;
    extern __shared__ float sm[];
    float* wsm = sm;
    float* pl = sm + WPAD;

    int tid = threadIdx.x;
    int b = blockIdx.z, x1 = blockIdx.y, bx = blockIdx.x;
    int half = tid / 144, u = tid % 144;
    int x3 = 2 * (u / 12), x4 = 2 * (u % 12);
    int x2 = bx * 2 + half;

    for (int i = tid; i < CIN * 81; i += 288) {
        float v = w[i];
        wsm[2 * i] = v; wsm[2 * i + 1] = v;
    }
    for (int i = tid; i < 2 * CIN * 26; i += 288) {
        int h = i / (CIN * 26), r = i % (CIN * 26);
        int ci = r / 26, rr = r % 26;
        float* rowp = pl + h * PLN + ci * CSTR + rr * RSTR;
        if (rr == 0 || rr == 25) {
            for (int c = 3; c <= 28; ++c) rowp[c] = 0.f;
        } else {
            rowp[3] = 0.f; rowp[28] = 0.f;
        }
    }

    u64 acc[2] = {0ull, 0ull};

    for (int j1 = 0; j1 < 3; ++j1) {
        int y1 = x1 + j1 - 1;
        if ((unsigned)y1 >= 24u) continue;
        for (int j2 = 0; j2 < 3; ++j2) {
            __syncthreads();
            for (int t = tid; t < 2 * CIN * 24; t += 288) {
                int h = t / (CIN * 24), r = t % (CIN * 24);
                int ci = r / 24, rr = 1 + r % 24;
                int y2 = bx * 2 + h + j2 - 1;
                float* dst = pl + h * PLN + ci * CSTR + rr * RSTR + 4;
                if ((unsigned)y2 < 24u) {
                    const float* src = in + ((((size_t)b * CIN + ci) * 24 + y1) * 24 + y2) * POOL_P
                                          + (rr - 1) * 24;
#pragma unroll
                    for (int c = 0; c < 6; ++c)
                        *(float4*)(dst + c * 4) = *(const float4*)(src + c * 4);
                } else {
                    float4 z = make_float4(0.f, 0.f, 0.f, 0.f);
#pragma unroll
                    for (int c = 0; c < 6; ++c) *(float4*)(dst + c * 4) = z;
                }
            }
            __syncthreads();

            const float* base = pl + half * PLN;
            for (int ci = 0; ci < CIN; ++ci) {
#pragma unroll
                for (int j3 = 0; j3 < 3; ++j3) {
                    const float* r0 = base + ci * CSTR + (x3 + j3) * RSTR + 3 + x4;
                    const float* r1 = r0 + RSTR;
                    u64 vd[4];
#pragma unroll
                    for (int t = 0; t < 4; ++t) vd[t] = pack2(r0[t], r1[t]);
                    const u64* wb = reinterpret_cast<const u64*>(
                        wsm + 2 * (ci * 81 + j1 * 27 + j2 * 9 + j3 * 3));
#pragma unroll
                    for (int j4 = 0; j4 < 3; ++j4) {
                        u64 wp = wb[j4];
                        fma2(acc[0], wp, vd[j4]);
                        fma2(acc[1], wp, vd[j4 + 1]);
                    }
                }
            }
        }
    }

    float b0 = bias[0];
    float2 c0 = unpack2(acc[0]);
    float2 c1 = unpack2(acc[1]);
    size_t base0 = (((size_t)b * 24 + x1) * 24 + x2) * POOL_P + x3 * 24 + x4;
    *(float2*)(out + base0)      = make_float2(fmaxf(c0.x + b0, 0.f), fmaxf(c1.x + b0, 0.f));
    *(float2*)(out + base0 + 24) = make_float2(fmaxf(c0.y + b0, 0.f), fmaxf(c1.y + b0, 0.f));
}

// host-side smem mirrors
static inline size_t conv_smem_bytes(int cin, int cout) {
    int cp2 = (cout + 1) & ~1;
    size_t wpad = ((size_t)cin * 81 * cp2 + 3) & ~(size_t)3;
    return (wpad + 2 * (size_t)cin * CSTR) * 4;
}
static inline size_t conv_cin1_smem_bytes(int cout) {
    int cp2 = (cout + 1) & ~1;
    size_t wpad = ((size_t)81 * cp2 + 3) & ~(size_t)3;
    return (wpad + 12 * (size_t)CSTR) * 4;
}
static inline size_t conv_c1_smem_bytes(int cin) {
    size_t wpad = (2 * (size_t)cin * 81 + 3) & ~(size_t)3;
    return (wpad + 2 * (size_t)cin * CSTR) * 4;
}

// ---------------------------------------------------------------------------
// Launch
// ---------------------------------------------------------------------------
extern "C" void kernel_launch(void* const* d_in, const int* in_sizes, int n_in,
                              void* d_out, int out_size) {
    const float* fA = (const float*)d_in[0];
    const float* fB = (const float*)d_in[1];
    const float* w1 = (const float*)d_in[2];
    const float* b1 = (const float*)d_in[3];
    const float* w2 = (const float*)d_in[4];
    const float* b2 = (const float*)d_in[5];
    const float* w3 = (const float*)d_in[6];
    const float* b3 = (const float*)d_in[7];
    float* out = (float*)d_out;

    float *gA, *gB, *invA, *invB, *cpool, *x1b, *x2b, *amax, *bmax;
    cudaGetSymbolAddress((void**)&gA, g_A);
    cudaGetSymbolAddress((void**)&gB, g_B);
    cudaGetSymbolAddress((void**)&invA, g_invnA);
    cudaGetSymbolAddress((void**)&invB, g_invnB);
    cudaGetSymbolAddress((void**)&cpool, g_cpool);
    cudaGetSymbolAddress((void**)&x1b, g_x1);
    cudaGetSymbolAddress((void**)&x2b, g_x2);
    cudaGetSymbolAddress((void**)&amax, g_amax);
    cudaGetSymbolAddress((void**)&bmax, g_bmax);

    size_t sm1 = conv_cin1_smem_bytes(10);   // ~48.2 KB
    size_t sm2 = conv_smem_bytes(10, 10);    // ~107.3 KB (2 CTAs/SM)
    size_t sm3 = conv_c1_smem_bytes(10);     // ~81.4 KB (2 CTAs/SM)
    size_t smg = 3 * 2 * STAGE_FLOATS * 4;   // 96 KB

    cudaFuncSetAttribute(gemm_pool_kernel, cudaFuncAttributeMaxDynamicSharedMemorySize, (int)smg);
    cudaFuncSetAttribute(conv4d_cin1_kernel<10>, cudaFuncAttributeMaxDynamicSharedMemorySize, (int)sm1);
    cudaFuncSetAttribute(conv4d_v4_kernel<10, 10>, cudaFuncAttributeMaxDynamicSharedMemorySize, (int)sm2);
    cudaFuncSetAttribute(conv4d_c1_kernel<10>, cudaFuncAttributeMaxDynamicSharedMemorySize, (int)sm3);

    // 1) inverse norms
    invnorm_kernel<<<(2 * BATCH * HW) / 256, 256>>>(fA, fB);

    // 2) transpose + normalize + tf32 round (A and B in ONE launch)
    transnorm_kernel<<<dim3(72, 32, 16), 256>>>(fA, fB, invA, invB, gA, gB);

    // 3) TF32 GEMM + pool + relu/L2
    gemm_pool_kernel<<<dim3(18, 18, BATCH), 128, smg>>>(gA, gB, cpool);

    // 4) mutual matching #1 (in place)
    cudaMemsetAsync(bmax, 0, BATCH * POOL_P * sizeof(float));
    maxfused_kernel<<<dim3(9, BATCH), 256>>>(cpool, amax, bmax);
    recip_kernel<<<(BATCH * POOL_P + 255) / 256, 256>>>(amax, bmax);
    mm_kernel<<<(POS_TOTAL / 4 + 255) / 256, 256>>>(cpool, amax, bmax, cpool);

    // 5) neighbourhood consensus convs
    dim3 cgrid(12, 24, BATCH);
    conv4d_cin1_kernel<10><<<cgrid, 288, sm1>>>(cpool, w1, b1, x1b);
    conv4d_v4_kernel<10, 10><<<cgrid, 288, sm2>>>(x1b, w2, b2, x2b);
    conv4d_c1_kernel<10><<<cgrid, 288, sm3>>>(x2b, w3, b3, cpool);

    // 6) mutual matching #2 -> output
    cudaMemsetAsync(bmax, 0, BATCH * POOL_P * sizeof(float));
    maxfused_kernel<<<dim3(9, BATCH), 256>>>(cpool, amax, bmax);
    recip_kernel<<<(BATCH * POOL_P + 255) / 256, 256>>>(amax, bmax);
    mm_kernel<<<(POS_TOTAL / 4 + 255) / 256, 256>>>(cpool, amax, bmax, out);

    (void)in_sizes; (void)n_in; (void)out_size;
}